// round 10
// baseline (speedup 1.0000x reference)
#include <cuda_runtime.h>
#include <cuda_bf16.h>
#include <cstdint>
#include <math.h>

#define ENC_LEN 2048
#define DEC_LEN 512
#define BATCH   32
#define HID     256
#define NEGVAL  (-1.0e12f)

// ---------------- static device scratch (allocation-free) ----------------
__device__ __align__(256) __nv_bfloat16 g_pHi[(size_t)BATCH * DEC_LEN * HID];  // proj hi [b][d][k]
__device__ __align__(256) __nv_bfloat16 g_pLo[(size_t)BATCH * DEC_LEN * HID];  // proj lo
__device__ __align__(256) __nv_bfloat16 g_eHi[(size_t)BATCH * ENC_LEN * HID];  // enc hi  [b][s][k]
__device__ __align__(256) __nv_bfloat16 g_eLo[(size_t)BATCH * ENC_LEN * HID];  // enc lo
__device__ __align__(256) __nv_bfloat16 g_dHi[(size_t)DEC_LEN * BATCH * HID];  // dec hi  [m][k]
__device__ __align__(256) __nv_bfloat16 g_dLo[(size_t)DEC_LEN * BATCH * HID];  // dec lo
__device__ __align__(256) __nv_bfloat16 g_wHi[(size_t)HID * HID];              // W^T hi [n][k]
__device__ __align__(256) __nv_bfloat16 g_wLo[(size_t)HID * HID];              // W^T lo

// ---------------- helpers ----------------
__device__ __forceinline__ uint32_t smem_u32(const void* p) {
    uint32_t a;
    asm("{ .reg .u64 t; cvta.to.shared.u64 t, %1; cvt.u32.u64 %0, t; }" : "=r"(a) : "l"(p));
    return a;
}
__device__ __forceinline__ void cp_async16(uint32_t saddr, const void* gaddr) {
    asm volatile("cp.async.cg.shared.global [%0], [%1], 16;" :: "r"(saddr), "l"(gaddr) : "memory");
}
__device__ __forceinline__ void cp_commit() { asm volatile("cp.async.commit_group;" ::: "memory"); }
template <int N>
__device__ __forceinline__ void cp_wait() { asm volatile("cp.async.wait_group %0;" :: "n"(N) : "memory"); }

__device__ __forceinline__ void ldsm4(uint32_t& r0, uint32_t& r1, uint32_t& r2, uint32_t& r3, uint32_t addr) {
    asm volatile("ldmatrix.sync.aligned.m8n8.x4.shared.b16 {%0,%1,%2,%3}, [%4];"
                 : "=r"(r0), "=r"(r1), "=r"(r2), "=r"(r3) : "r"(addr));
}
__device__ __forceinline__ void mma_bf16(float* c, const uint32_t* a, const uint32_t* b) {
    asm volatile(
        "mma.sync.aligned.m16n8k16.row.col.f32.bf16.bf16.f32 "
        "{%0,%1,%2,%3}, {%4,%5,%6,%7}, {%8,%9}, {%0,%1,%2,%3};"
        : "+f"(c[0]), "+f"(c[1]), "+f"(c[2]), "+f"(c[3])
        : "r"(a[0]), "r"(a[1]), "r"(a[2]), "r"(a[3]), "r"(b[0]), "r"(b[1]));
}

__device__ __forceinline__ void bf16_split4(float4 v, uint2& hi, uint2& lo) {
    __nv_bfloat16 hx = __float2bfloat16_rn(v.x), hy = __float2bfloat16_rn(v.y);
    __nv_bfloat16 hz = __float2bfloat16_rn(v.z), hw = __float2bfloat16_rn(v.w);
    __nv_bfloat16 lx = __float2bfloat16_rn(v.x - __bfloat162float(hx));
    __nv_bfloat16 ly = __float2bfloat16_rn(v.y - __bfloat162float(hy));
    __nv_bfloat16 lz = __float2bfloat16_rn(v.z - __bfloat162float(hz));
    __nv_bfloat16 lw = __float2bfloat16_rn(v.w - __bfloat162float(hw));
    __nv_bfloat162 h01 = __halves2bfloat162(hx, hy), h23 = __halves2bfloat162(hz, hw);
    __nv_bfloat162 l01 = __halves2bfloat162(lx, ly), l23 = __halves2bfloat162(lz, lw);
    hi.x = *reinterpret_cast<uint32_t*>(&h01); hi.y = *reinterpret_cast<uint32_t*>(&h23);
    lo.x = *reinterpret_cast<uint32_t*>(&l01); lo.y = *reinterpret_cast<uint32_t*>(&l23);
}
__device__ __forceinline__ uint32_t bf16_split2(float a, float b, uint32_t& lo) {
    __nv_bfloat16 ha = __float2bfloat16_rn(a), hb = __float2bfloat16_rn(b);
    __nv_bfloat16 la = __float2bfloat16_rn(a - __bfloat162float(ha));
    __nv_bfloat16 lb = __float2bfloat16_rn(b - __bfloat162float(hb));
    __nv_bfloat162 h = __halves2bfloat162(ha, hb), l = __halves2bfloat162(la, lb);
    lo = *reinterpret_cast<uint32_t*>(&l);
    return *reinterpret_cast<uint32_t*>(&h);
}

// =====================================================================
// Kernel 0a: enc (s,b,h) f32 -> bf16 hi/lo [b][s][h]   (side stream)
// =====================================================================
__global__ __launch_bounds__(256)
void k_prep_enc(const float* __restrict__ enc) {
    size_t fid = (size_t)blockIdx.x * 256 + threadIdx.x;
    int h4 = (int)(fid & 63);
    int sb = (int)(fid >> 6);
    int b = sb & 31;
    int s = sb >> 5;
    float4 v = reinterpret_cast<const float4*>(enc)[fid];
    uint2 hi, lo;
    bf16_split4(v, hi, lo);
    size_t o = ((size_t)b * ENC_LEN + s) * 64 + h4;
    reinterpret_cast<uint2*>(g_eHi)[o] = hi;
    reinterpret_cast<uint2*>(g_eLo)[o] = lo;
}

// =====================================================================
// Kernel 0b: fused dec split + W transpose/split
// =====================================================================
#define NDEC_BLOCKS ((DEC_LEN * BATCH * HID / 4) / 256)
__global__ __launch_bounds__(256)
void k_prep_decw(const float* __restrict__ dec, const float* __restrict__ W) {
    if (blockIdx.x < NDEC_BLOCKS) {
        size_t fid = (size_t)blockIdx.x * 256 + threadIdx.x;
        float4 v = reinterpret_cast<const float4*>(dec)[fid];
        uint2 hi, lo;
        bf16_split4(v, hi, lo);
        reinterpret_cast<uint2*>(g_dHi)[fid] = hi;
        reinterpret_cast<uint2*>(g_dLo)[fid] = lo;
    } else {
        int n = blockIdx.x - NDEC_BLOCKS;
        int k = threadIdx.x;
        float v = W[(size_t)k * HID + n];
        __nv_bfloat16 h = __float2bfloat16_rn(v);
        __nv_bfloat16 l = __float2bfloat16_rn(v - __bfloat162float(h));
        g_wHi[(size_t)n * HID + k] = h;
        g_wLo[(size_t)n * HID + k] = l;
    }
}

// =====================================================================
// tile machinery: CTA tile 128(m) x 128(n), K chunks of 32 (64B rows),
// 3-stage cp.async pipeline, 32KB/stage -> 2 CTAs/SM (16 warps/SM).
// swizzle: off = row*64 + ((seg ^ ((row>>1)&3)) << 4), seg in 0..3
// =====================================================================
#define STAGE_BYTES 32768
#define AH_OFF 0
#define AL_OFF 8192
#define BH_OFF 16384
#define BL_OFF 24576
#define SMEM_TOTAL (3 * STAGE_BYTES + 1024)

// =====================================================================
// Kernel 1: proj = dec @ W^T(T) via bf16 split-4 (hh+hl+lh+ll) MMA
// =====================================================================
__global__ __launch_bounds__(256, 2)
void k_proj_mma() {
    extern __shared__ char dynsmem[];
    const int tid = threadIdx.x;
    const int wid = tid >> 5, lane = tid & 31;
    const int wm = wid & 3;
    const int wn = wid >> 2;
    const int n0 = blockIdx.x * 128;
    const int m0 = blockIdx.y * 128;

    uint32_t buf = (smem_u32(dynsmem) + 1023u) & ~1023u;

    const __nv_bfloat16* Ah = g_dHi + (size_t)m0 * HID;
    const __nv_bfloat16* Al = g_dLo + (size_t)m0 * HID;
    const __nv_bfloat16* Bh = g_wHi + (size_t)n0 * HID;
    const __nv_bfloat16* Bl = g_wLo + (size_t)n0 * HID;

    auto load_stage = [&](int c, int slot) {
        uint32_t sb = buf + slot * STAGE_BYTES;
        int kofs = c * 32;
#pragma unroll
        for (int i = 0; i < 2; i++) {
            int id = tid + i * 256;
            int row = id >> 2, seg = id & 3;
            uint32_t so = (uint32_t)(row * 64 + ((seg ^ ((row >> 1) & 3)) << 4));
            size_t go = (size_t)row * HID + kofs + seg * 8;
            cp_async16(sb + AH_OFF + so, Ah + go);
            cp_async16(sb + AL_OFF + so, Al + go);
            cp_async16(sb + BH_OFF + so, Bh + go);
            cp_async16(sb + BL_OFF + so, Bl + go);
        }
        cp_commit();
    };

    float acc[2][8][4];
#pragma unroll
    for (int mi = 0; mi < 2; mi++)
#pragma unroll
        for (int nj = 0; nj < 8; nj++)
#pragma unroll
            for (int r = 0; r < 4; r++) acc[mi][nj][r] = 0.f;

    uint32_t aRow[2], aXor[2];
#pragma unroll
    for (int mi = 0; mi < 2; mi++) {
        int r = wm * 32 + mi * 16 + (lane & 15);
        aRow[mi] = (uint32_t)(r * 64);
        aXor[mi] = (uint32_t)((r >> 1) & 3);
    }
    uint32_t bRow[4], bXor[4];
#pragma unroll
    for (int nt = 0; nt < 4; nt++) {
        int r = wn * 64 + nt * 16 + (lane & 7) + ((lane >> 4) << 3);
        bRow[nt] = (uint32_t)(r * 64);
        bXor[nt] = (uint32_t)((r >> 1) & 3);
    }
    const uint32_t aSegBase = (uint32_t)(lane >> 4);
    const uint32_t bSegBase = (uint32_t)((lane >> 3) & 1);

    load_stage(0, 0);
    load_stage(1, 1);
    load_stage(2, 2);

    for (int c = 0; c < 8; c++) {
        if (c < 6) cp_wait<2>(); else if (c == 6) cp_wait<1>(); else cp_wait<0>();
        __syncthreads();
        uint32_t sb = buf + (c % 3) * STAGE_BYTES;
#pragma unroll
        for (int ks = 0; ks < 2; ks++) {
            uint32_t ah[2][4], al[2][4], bb[8][2];
            uint32_t aseg = (uint32_t)(ks * 2) + aSegBase;
            uint32_t bseg = (uint32_t)(ks * 2) + bSegBase;
#pragma unroll
            for (int mi = 0; mi < 2; mi++) {
                uint32_t ad = sb + AH_OFF + aRow[mi] + (((aseg ^ aXor[mi])) << 4);
                ldsm4(ah[mi][0], ah[mi][1], ah[mi][2], ah[mi][3], ad);
                ad = sb + AL_OFF + aRow[mi] + (((aseg ^ aXor[mi])) << 4);
                ldsm4(al[mi][0], al[mi][1], al[mi][2], al[mi][3], ad);
            }
#pragma unroll
            for (int nt = 0; nt < 4; nt++) {
                uint32_t bd = sb + BH_OFF + bRow[nt] + (((bseg ^ bXor[nt])) << 4);
                ldsm4(bb[nt * 2][0], bb[nt * 2][1], bb[nt * 2 + 1][0], bb[nt * 2 + 1][1], bd);
            }
#pragma unroll
            for (int mi = 0; mi < 2; mi++)
#pragma unroll
                for (int nj = 0; nj < 8; nj++) mma_bf16(acc[mi][nj], ah[mi], bb[nj]);
#pragma unroll
            for (int mi = 0; mi < 2; mi++)
#pragma unroll
                for (int nj = 0; nj < 8; nj++) mma_bf16(acc[mi][nj], al[mi], bb[nj]);
#pragma unroll
            for (int nt = 0; nt < 4; nt++) {
                uint32_t bd = sb + BL_OFF + bRow[nt] + (((bseg ^ bXor[nt])) << 4);
                ldsm4(bb[nt * 2][0], bb[nt * 2][1], bb[nt * 2 + 1][0], bb[nt * 2 + 1][1], bd);
            }
#pragma unroll
            for (int mi = 0; mi < 2; mi++)
#pragma unroll
                for (int nj = 0; nj < 8; nj++) mma_bf16(acc[mi][nj], ah[mi], bb[nj]);
#pragma unroll
            for (int mi = 0; mi < 2; mi++)
#pragma unroll
                for (int nj = 0; nj < 8; nj++) mma_bf16(acc[mi][nj], al[mi], bb[nj]);
        }
        __syncthreads();
        if (c + 3 < 8) load_stage(c + 3, (c + 3) % 3);
    }

    const int grp = lane >> 2, qd = lane & 3;
#pragma unroll
    for (int mi = 0; mi < 2; mi++) {
        int m0r = m0 + wm * 32 + mi * 16 + grp;
        int m1r = m0r + 8;
        int d0v = m0r >> 5, b0v = m0r & 31;
        int d1v = m1r >> 5, b1v = m1r & 31;
        size_t r0 = ((size_t)b0v * DEC_LEN + d0v) * HID;
        size_t r1 = ((size_t)b1v * DEC_LEN + d1v) * HID;
#pragma unroll
        for (int nj = 0; nj < 8; nj++) {
            int cl = n0 + wn * 64 + nj * 8 + qd * 2;
            uint32_t lo;
            uint32_t hi = bf16_split2(acc[mi][nj][0], acc[mi][nj][1], lo);
            *reinterpret_cast<uint32_t*>(&g_pHi[r0 + cl]) = hi;
            *reinterpret_cast<uint32_t*>(&g_pLo[r0 + cl]) = lo;
            hi = bf16_split2(acc[mi][nj][2], acc[mi][nj][3], lo);
            *reinterpret_cast<uint32_t*>(&g_pHi[r1 + cl]) = hi;
            *reinterpret_cast<uint32_t*>(&g_pLo[r1 + cl]) = lo;
        }
    }
}

// =====================================================================
// Kernel 2: score via mma.sync bf16 split-3 (hh + hl + lh)
// b_base selects the batch quarter (8 batches per launch).
// =====================================================================
__global__ __launch_bounds__(256, 2)
void k_score_mma(const int* __restrict__ mask, float* __restrict__ wout, int b_base) {
    extern __shared__ char dynsmem[];
    __shared__ int mk[128];
    const int tid = threadIdx.x;
    const int wid = tid >> 5, lane = tid & 31;
    const int wm = wid & 3;
    const int wn = wid >> 2;
    const int b = b_base + blockIdx.z;
    const int d0 = blockIdx.y * 128;
    const int s0 = blockIdx.x * 128;

    uint32_t buf = (smem_u32(dynsmem) + 1023u) & ~1023u;

    if (tid < 128) mk[tid] = mask[(size_t)(s0 + tid) * BATCH + b];

    const __nv_bfloat16* Ah = g_pHi + ((size_t)b * DEC_LEN + d0) * HID;
    const __nv_bfloat16* Al = g_pLo + ((size_t)b * DEC_LEN + d0) * HID;
    const __nv_bfloat16* Bh = g_eHi + ((size_t)b * ENC_LEN + s0) * HID;
    const __nv_bfloat16* Bl = g_eLo + ((size_t)b * ENC_LEN + s0) * HID;

    auto load_stage = [&](int c, int slot) {
        uint32_t sb = buf + slot * STAGE_BYTES;
        int kofs = c * 32;
#pragma unroll
        for (int i = 0; i < 2; i++) {
            int id = tid + i * 256;
            int row = id >> 2, seg = id & 3;
            uint32_t so = (uint32_t)(row * 64 + ((seg ^ ((row >> 1) & 3)) << 4));
            size_t go = (size_t)row * HID + kofs + seg * 8;
            cp_async16(sb + AH_OFF + so, Ah + go);
            cp_async16(sb + AL_OFF + so, Al + go);
            cp_async16(sb + BH_OFF + so, Bh + go);
            cp_async16(sb + BL_OFF + so, Bl + go);
        }
        cp_commit();
    };

    float acc[2][8][4];
#pragma unroll
    for (int mi = 0; mi < 2; mi++)
#pragma unroll
        for (int nj = 0; nj < 8; nj++)
#pragma unroll
            for (int r = 0; r < 4; r++) acc[mi][nj][r] = 0.f;

    uint32_t aRow[2], aXor[2];
#pragma unroll
    for (int mi = 0; mi < 2; mi++) {
        int r = wm * 32 + mi * 16 + (lane & 15);
        aRow[mi] = (uint32_t)(r * 64);
        aXor[mi] = (uint32_t)((r >> 1) & 3);
    }
    uint32_t bRow[4], bXor[4];
#pragma unroll
    for (int nt = 0; nt < 4; nt++) {
        int r = wn * 64 + nt * 16 + (lane & 7) + ((lane >> 4) << 3);
        bRow[nt] = (uint32_t)(r * 64);
        bXor[nt] = (uint32_t)((r >> 1) & 3);
    }
    const uint32_t aSegBase = (uint32_t)(lane >> 4);
    const uint32_t bSegBase = (uint32_t)((lane >> 3) & 1);

    load_stage(0, 0);
    load_stage(1, 1);
    load_stage(2, 2);

    for (int c = 0; c < 8; c++) {
        if (c < 6) cp_wait<2>(); else if (c == 6) cp_wait<1>(); else cp_wait<0>();
        __syncthreads();
        uint32_t sb = buf + (c % 3) * STAGE_BYTES;
#pragma unroll
        for (int ks = 0; ks < 2; ks++) {
            uint32_t ah[2][4], al[2][4], bb[8][2];
            uint32_t aseg = (uint32_t)(ks * 2) + aSegBase;
            uint32_t bseg = (uint32_t)(ks * 2) + bSegBase;
#pragma unroll
            for (int mi = 0; mi < 2; mi++) {
                uint32_t ad = sb + AH_OFF + aRow[mi] + (((aseg ^ aXor[mi])) << 4);
                ldsm4(ah[mi][0], ah[mi][1], ah[mi][2], ah[mi][3], ad);
                ad = sb + AL_OFF + aRow[mi] + (((aseg ^ aXor[mi])) << 4);
                ldsm4(al[mi][0], al[mi][1], al[mi][2], al[mi][3], ad);
            }
#pragma unroll
            for (int nt = 0; nt < 4; nt++) {
                uint32_t bd = sb + BH_OFF + bRow[nt] + (((bseg ^ bXor[nt])) << 4);
                ldsm4(bb[nt * 2][0], bb[nt * 2][1], bb[nt * 2 + 1][0], bb[nt * 2 + 1][1], bd);
            }
#pragma unroll
            for (int mi = 0; mi < 2; mi++)
#pragma unroll
                for (int nj = 0; nj < 8; nj++) mma_bf16(acc[mi][nj], ah[mi], bb[nj]);
#pragma unroll
            for (int mi = 0; mi < 2; mi++)
#pragma unroll
                for (int nj = 0; nj < 8; nj++) mma_bf16(acc[mi][nj], al[mi], bb[nj]);
#pragma unroll
            for (int nt = 0; nt < 4; nt++) {
                uint32_t bd = sb + BL_OFF + bRow[nt] + (((bseg ^ bXor[nt])) << 4);
                ldsm4(bb[nt * 2][0], bb[nt * 2][1], bb[nt * 2 + 1][0], bb[nt * 2 + 1][1], bd);
            }
#pragma unroll
            for (int mi = 0; mi < 2; mi++)
#pragma unroll
                for (int nj = 0; nj < 8; nj++) mma_bf16(acc[mi][nj], ah[mi], bb[nj]);
        }
        __syncthreads();
        if (c + 3 < 8) load_stage(c + 3, (c + 3) % 3);
    }

    const int grp = lane >> 2, qd = lane & 3;
#pragma unroll
    for (int mi = 0; mi < 2; mi++) {
        int dr0 = d0 + wm * 32 + mi * 16 + grp;
        int dr1 = dr0 + 8;
        size_t row0 = ((size_t)b * DEC_LEN + dr0) * (size_t)ENC_LEN;
        size_t row1 = ((size_t)b * DEC_LEN + dr1) * (size_t)ENC_LEN;
#pragma unroll
        for (int nj = 0; nj < 8; nj++) {
            int cl = wn * 64 + nj * 8 + qd * 2;
            int m0v = mk[cl], m1v = mk[cl + 1];
            int s = s0 + cl;
            float2 v0, v1;
            v0.x = m0v ? acc[mi][nj][0] : NEGVAL;
            v0.y = m1v ? acc[mi][nj][1] : NEGVAL;
            v1.x = m0v ? acc[mi][nj][2] : NEGVAL;
            v1.y = m1v ? acc[mi][nj][3] : NEGVAL;
            *reinterpret_cast<float2*>(&wout[row0 + s]) = v0;
            *reinterpret_cast<float2*>(&wout[row1 + s]) = v1;
        }
    }
}

// =====================================================================
// Kernel 3: softmax + sparse attn (significant-only __expf)
// r_base selects the row quarter (8 batches * 512 rows per launch).
// =====================================================================
__global__ __launch_bounds__(256)
void k_softmax_attn(const float* __restrict__ enc, float* __restrict__ wts,
                    float* __restrict__ attn, int r_base) {
    const int r = r_base + blockIdx.x;
    const int b = r >> 9;
    const int d = r & 511;
    float* row = wts + (size_t)r * ENC_LEN;
    const int tid = threadIdx.x;
    const int lane = tid & 31, warp = tid >> 5;

    float4 v0 = *reinterpret_cast<const float4*>(&row[tid * 8]);
    float4 v1 = *reinterpret_cast<const float4*>(&row[tid * 8 + 4]);
    float va[8] = {v0.x, v0.y, v0.z, v0.w, v1.x, v1.y, v1.z, v1.w};

    __shared__ float redm[8];
    __shared__ float reds[8];
    __shared__ int cnt;
    __shared__ int sidx[256];
    __shared__ float sw[256];
    if (tid == 0) cnt = 0;

    float m = va[0];
#pragma unroll
    for (int j = 1; j < 8; j++) m = fmaxf(m, va[j]);
#pragma unroll
    for (int o = 16; o; o >>= 1) m = fmaxf(m, __shfl_xor_sync(0xffffffffu, m, o));
    if (lane == 0) redm[warp] = m;
    __syncthreads();
    if (tid < 32) {
        float t = (lane < 8) ? redm[lane] : -3.4e38f;
#pragma unroll
        for (int o = 4; o; o >>= 1) t = fmaxf(t, __shfl_xor_sync(0xffffffffu, t, o));
        if (lane == 0) redm[0] = t;
    }
    __syncthreads();
    const float mx = redm[0];

    float e[8];
    float s = 0.f;
#pragma unroll
    for (int j = 0; j < 8; j++) {
        float x = va[j] - mx;
        e[j] = (x > -30.0f) ? __expf(x) : 0.f;
        s += e[j];
    }
#pragma unroll
    for (int o = 16; o; o >>= 1) s += __shfl_xor_sync(0xffffffffu, s, o);
    if (lane == 0) reds[warp] = s;
    __syncthreads();
    if (tid < 32) {
        float t = (lane < 8) ? reds[lane] : 0.f;
#pragma unroll
        for (int o = 4; o; o >>= 1) t += __shfl_xor_sync(0xffffffffu, t, o);
        if (lane == 0) reds[0] = t;
    }
    __syncthreads();
    const float inv = 1.0f / reds[0];

    float w[8];
#pragma unroll
    for (int j = 0; j < 8; j++) {
        w[j] = e[j] * inv;
        if (e[j] > 0.f) {
            int p = atomicAdd(&cnt, 1);
            if (p < 256) { sidx[p] = tid * 8 + j; sw[p] = w[j]; }
        }
    }
    float4 o0 = make_float4(w[0], w[1], w[2], w[3]);
    float4 o1 = make_float4(w[4], w[5], w[6], w[7]);
    *reinterpret_cast<float4*>(&row[tid * 8]) = o0;
    *reinterpret_cast<float4*>(&row[tid * 8 + 4]) = o1;
    __syncthreads();

    int n = cnt; if (n > 256) n = 256;
    float a = 0.f;
    for (int i = 0; i < n; i++) {
        a += sw[i] * enc[((size_t)sidx[i] * BATCH + b) * HID + tid];
    }
    attn[((size_t)d * BATCH + b) * HID + tid] = a;
}

// =====================================================================
extern "C" void kernel_launch(void* const* d_in, const int* in_sizes, int n_in,
                              void* d_out, int out_size) {
    const float* enc = (const float*)d_in[0];   // (2048, 32, 256)
    const float* dec = (const float*)d_in[1];   // (512, 32, 256)
    const float* W   = (const float*)d_in[2];   // (256, 256)
    const int* mask  = (const int*)d_in[3];     // (2048, 32)

    float* attn = (float*)d_out;
    float* wts  = (float*)d_out + (size_t)DEC_LEN * BATCH * HID;

    static cudaStream_t s_side = nullptr;
    static cudaEvent_t s_evFork = nullptr, s_evJoin = nullptr, s_evEnd = nullptr;
    static cudaEvent_t s_evQ[4] = {nullptr, nullptr, nullptr, nullptr};
    if (s_side == nullptr) {
        cudaStreamCreateWithFlags(&s_side, cudaStreamNonBlocking);
        cudaEventCreateWithFlags(&s_evFork, cudaEventDisableTiming);
        cudaEventCreateWithFlags(&s_evJoin, cudaEventDisableTiming);
        cudaEventCreateWithFlags(&s_evEnd, cudaEventDisableTiming);
        for (int q = 0; q < 4; q++)
            cudaEventCreateWithFlags(&s_evQ[q], cudaEventDisableTiming);
        cudaFuncSetAttribute(k_score_mma, cudaFuncAttributeMaxDynamicSharedMemorySize, SMEM_TOTAL);
        cudaFuncSetAttribute(k_proj_mma, cudaFuncAttributeMaxDynamicSharedMemorySize, SMEM_TOTAL);
    }

    // fork: prep_enc on side stream alongside dec/W prep + proj on main.
    cudaEventRecord(s_evFork, 0);
    cudaStreamWaitEvent(s_side, s_evFork, 0);
    k_prep_enc<<<(ENC_LEN * BATCH * HID / 4) / 256, 256, 0, s_side>>>(enc);
    cudaEventRecord(s_evJoin, s_side);

    k_prep_decw<<<NDEC_BLOCKS + HID, 256>>>(dec, W);
    k_proj_mma<<<dim3(HID / 128, (DEC_LEN * BATCH) / 128), 256, SMEM_TOTAL>>>();
    cudaStreamWaitEvent(0, s_evJoin, 0);

    // batch-quarter pipeline: softmax(q) on side stream overlaps score(q+1)
    // on main stream. score is tensor-bound at occ 24%; softmax is DRAM-bound
    // with small footprint -> co-resident.
    for (int q = 0; q < 4; q++) {
        k_score_mma<<<dim3(ENC_LEN / 128, DEC_LEN / 128, BATCH / 4), 256,
                      SMEM_TOTAL>>>(mask, wts, q * (BATCH / 4));
        cudaEventRecord(s_evQ[q], 0);
        cudaStreamWaitEvent(s_side, s_evQ[q], 0);
        k_softmax_attn<<<(BATCH / 4) * DEC_LEN, 256, 0, s_side>>>(
            enc, wts, attn, q * (BATCH / 4) * DEC_LEN);
    }
    cudaEventRecord(s_evEnd, s_side);
    cudaStreamWaitEvent(0, s_evEnd, 0);
}

// round 11
// speedup vs baseline: 1.0532x; 1.0532x over previous
#include <cuda_runtime.h>
#include <cuda_bf16.h>
#include <cstdint>
#include <math.h>

#define ENC_LEN 2048
#define DEC_LEN 512
#define BATCH   32
#define HID     256
#define NEGVAL  (-1.0e12f)

// ---------------- static device scratch (allocation-free) ----------------
__device__ __align__(256) __nv_bfloat16 g_pHi[(size_t)BATCH * DEC_LEN * HID];  // proj hi [b][d][k]
__device__ __align__(256) __nv_bfloat16 g_pLo[(size_t)BATCH * DEC_LEN * HID];  // proj lo
__device__ __align__(256) __nv_bfloat16 g_eHi[(size_t)BATCH * ENC_LEN * HID];  // enc hi  [b][s][k]
__device__ __align__(256) __nv_bfloat16 g_eLo[(size_t)BATCH * ENC_LEN * HID];  // enc lo
__device__ __align__(256) __nv_bfloat16 g_dHi[(size_t)DEC_LEN * BATCH * HID];  // dec hi  [m][k]
__device__ __align__(256) __nv_bfloat16 g_dLo[(size_t)DEC_LEN * BATCH * HID];  // dec lo
__device__ __align__(256) __nv_bfloat16 g_wHi[(size_t)HID * HID];              // W^T hi [n][k]
__device__ __align__(256) __nv_bfloat16 g_wLo[(size_t)HID * HID];              // W^T lo

// ---------------- helpers ----------------
__device__ __forceinline__ uint32_t smem_u32(const void* p) {
    uint32_t a;
    asm("{ .reg .u64 t; cvta.to.shared.u64 t, %1; cvt.u32.u64 %0, t; }" : "=r"(a) : "l"(p));
    return a;
}
__device__ __forceinline__ void cp_async16(uint32_t saddr, const void* gaddr) {
    asm volatile("cp.async.cg.shared.global [%0], [%1], 16;" :: "r"(saddr), "l"(gaddr) : "memory");
}
__device__ __forceinline__ void cp_commit() { asm volatile("cp.async.commit_group;" ::: "memory"); }
template <int N>
__device__ __forceinline__ void cp_wait() { asm volatile("cp.async.wait_group %0;" :: "n"(N) : "memory"); }

__device__ __forceinline__ void ldsm4(uint32_t& r0, uint32_t& r1, uint32_t& r2, uint32_t& r3, uint32_t addr) {
    asm volatile("ldmatrix.sync.aligned.m8n8.x4.shared.b16 {%0,%1,%2,%3}, [%4];"
                 : "=r"(r0), "=r"(r1), "=r"(r2), "=r"(r3) : "r"(addr));
}
__device__ __forceinline__ void mma_bf16(float* c, const uint32_t* a, const uint32_t* b) {
    asm volatile(
        "mma.sync.aligned.m16n8k16.row.col.f32.bf16.bf16.f32 "
        "{%0,%1,%2,%3}, {%4,%5,%6,%7}, {%8,%9}, {%0,%1,%2,%3};"
        : "+f"(c[0]), "+f"(c[1]), "+f"(c[2]), "+f"(c[3])
        : "r"(a[0]), "r"(a[1]), "r"(a[2]), "r"(a[3]), "r"(b[0]), "r"(b[1]));
}

__device__ __forceinline__ void bf16_split4(float4 v, uint2& hi, uint2& lo) {
    __nv_bfloat16 hx = __float2bfloat16_rn(v.x), hy = __float2bfloat16_rn(v.y);
    __nv_bfloat16 hz = __float2bfloat16_rn(v.z), hw = __float2bfloat16_rn(v.w);
    __nv_bfloat16 lx = __float2bfloat16_rn(v.x - __bfloat162float(hx));
    __nv_bfloat16 ly = __float2bfloat16_rn(v.y - __bfloat162float(hy));
    __nv_bfloat16 lz = __float2bfloat16_rn(v.z - __bfloat162float(hz));
    __nv_bfloat16 lw = __float2bfloat16_rn(v.w - __bfloat162float(hw));
    __nv_bfloat162 h01 = __halves2bfloat162(hx, hy), h23 = __halves2bfloat162(hz, hw);
    __nv_bfloat162 l01 = __halves2bfloat162(lx, ly), l23 = __halves2bfloat162(lz, lw);
    hi.x = *reinterpret_cast<uint32_t*>(&h01); hi.y = *reinterpret_cast<uint32_t*>(&h23);
    lo.x = *reinterpret_cast<uint32_t*>(&l01); lo.y = *reinterpret_cast<uint32_t*>(&l23);
}
__device__ __forceinline__ uint32_t bf16_split2(float a, float b, uint32_t& lo) {
    __nv_bfloat16 ha = __float2bfloat16_rn(a), hb = __float2bfloat16_rn(b);
    __nv_bfloat16 la = __float2bfloat16_rn(a - __bfloat162float(ha));
    __nv_bfloat16 lb = __float2bfloat16_rn(b - __bfloat162float(hb));
    __nv_bfloat162 h = __halves2bfloat162(ha, hb), l = __halves2bfloat162(la, lb);
    lo = *reinterpret_cast<uint32_t*>(&l);
    return *reinterpret_cast<uint32_t*>(&h);
}

// =====================================================================
// Kernel 0a: enc (s,b,h) f32 -> bf16 hi/lo [b][s][h]
// =====================================================================
__global__ __launch_bounds__(256)
void k_prep_enc(const float* __restrict__ enc) {
    size_t fid = (size_t)blockIdx.x * 256 + threadIdx.x;
    int h4 = (int)(fid & 63);
    int sb = (int)(fid >> 6);
    int b = sb & 31;
    int s = sb >> 5;
    float4 v = reinterpret_cast<const float4*>(enc)[fid];
    uint2 hi, lo;
    bf16_split4(v, hi, lo);
    size_t o = ((size_t)b * ENC_LEN + s) * 64 + h4;
    reinterpret_cast<uint2*>(g_eHi)[o] = hi;
    reinterpret_cast<uint2*>(g_eLo)[o] = lo;
}

// =====================================================================
// Kernel 0b: fused dec split + W transpose/split
// =====================================================================
#define NDEC_BLOCKS ((DEC_LEN * BATCH * HID / 4) / 256)
__global__ __launch_bounds__(256)
void k_prep_decw(const float* __restrict__ dec, const float* __restrict__ W) {
    if (blockIdx.x < NDEC_BLOCKS) {
        size_t fid = (size_t)blockIdx.x * 256 + threadIdx.x;
        float4 v = reinterpret_cast<const float4*>(dec)[fid];
        uint2 hi, lo;
        bf16_split4(v, hi, lo);
        reinterpret_cast<uint2*>(g_dHi)[fid] = hi;
        reinterpret_cast<uint2*>(g_dLo)[fid] = lo;
    } else {
        int n = blockIdx.x - NDEC_BLOCKS;
        int k = threadIdx.x;
        float v = W[(size_t)k * HID + n];
        __nv_bfloat16 h = __float2bfloat16_rn(v);
        __nv_bfloat16 l = __float2bfloat16_rn(v - __bfloat162float(h));
        g_wHi[(size_t)n * HID + k] = h;
        g_wLo[(size_t)n * HID + k] = l;
    }
}

// =====================================================================
// tile machinery: CTA tile 128(m) x 128(n), K chunks of 32 (64B rows),
// 3-stage cp.async pipeline with SINGLE barrier per chunk:
//   wait<1> -> sync -> prefetch(c+2) into slot just released -> compute(c)
// 32KB/stage -> 2 CTAs/SM (16 warps/SM).
// swizzle: off = row*64 + ((seg ^ ((row>>1)&3)) << 4), seg in 0..3
// =====================================================================
#define STAGE_BYTES 32768
#define AH_OFF 0
#define AL_OFF 8192
#define BH_OFF 16384
#define BL_OFF 24576
#define SMEM_TOTAL (3 * STAGE_BYTES + 1024)

// =====================================================================
// Kernel 1: proj = dec @ W^T(T) via bf16 split-4 (hh+hl+lh+ll) MMA
// =====================================================================
__global__ __launch_bounds__(256, 2)
void k_proj_mma() {
    extern __shared__ char dynsmem[];
    const int tid = threadIdx.x;
    const int wid = tid >> 5, lane = tid & 31;
    const int wm = wid & 3;
    const int wn = wid >> 2;
    const int n0 = blockIdx.x * 128;
    const int m0 = blockIdx.y * 128;

    uint32_t buf = (smem_u32(dynsmem) + 1023u) & ~1023u;

    const __nv_bfloat16* Ah = g_dHi + (size_t)m0 * HID;
    const __nv_bfloat16* Al = g_dLo + (size_t)m0 * HID;
    const __nv_bfloat16* Bh = g_wHi + (size_t)n0 * HID;
    const __nv_bfloat16* Bl = g_wLo + (size_t)n0 * HID;

    auto load_stage = [&](int c, int slot) {
        uint32_t sb = buf + slot * STAGE_BYTES;
        int kofs = c * 32;
#pragma unroll
        for (int i = 0; i < 2; i++) {
            int id = tid + i * 256;
            int row = id >> 2, seg = id & 3;
            uint32_t so = (uint32_t)(row * 64 + ((seg ^ ((row >> 1) & 3)) << 4));
            size_t go = (size_t)row * HID + kofs + seg * 8;
            cp_async16(sb + AH_OFF + so, Ah + go);
            cp_async16(sb + AL_OFF + so, Al + go);
            cp_async16(sb + BH_OFF + so, Bh + go);
            cp_async16(sb + BL_OFF + so, Bl + go);
        }
        cp_commit();
    };

    float acc[2][8][4];
#pragma unroll
    for (int mi = 0; mi < 2; mi++)
#pragma unroll
        for (int nj = 0; nj < 8; nj++)
#pragma unroll
            for (int r = 0; r < 4; r++) acc[mi][nj][r] = 0.f;

    uint32_t aRow[2], aXor[2];
#pragma unroll
    for (int mi = 0; mi < 2; mi++) {
        int r = wm * 32 + mi * 16 + (lane & 15);
        aRow[mi] = (uint32_t)(r * 64);
        aXor[mi] = (uint32_t)((r >> 1) & 3);
    }
    uint32_t bRow[4], bXor[4];
#pragma unroll
    for (int nt = 0; nt < 4; nt++) {
        int r = wn * 64 + nt * 16 + (lane & 7) + ((lane >> 4) << 3);
        bRow[nt] = (uint32_t)(r * 64);
        bXor[nt] = (uint32_t)((r >> 1) & 3);
    }
    const uint32_t aSegBase = (uint32_t)(lane >> 4);
    const uint32_t bSegBase = (uint32_t)((lane >> 3) & 1);

    load_stage(0, 0);
    load_stage(1, 1);

    for (int c = 0; c < 8; c++) {
        if (c < 7) cp_wait<1>(); else cp_wait<0>();
        __syncthreads();                      // chunk c-1 consumers done
        if (c + 2 < 8) load_stage(c + 2, (c + 2) % 3);   // reuse released slot
        uint32_t sb = buf + (c % 3) * STAGE_BYTES;
#pragma unroll
        for (int ks = 0; ks < 2; ks++) {
            uint32_t ah[2][4], al[2][4], bb[8][2];
            uint32_t aseg = (uint32_t)(ks * 2) + aSegBase;
            uint32_t bseg = (uint32_t)(ks * 2) + bSegBase;
#pragma unroll
            for (int mi = 0; mi < 2; mi++) {
                uint32_t ad = sb + AH_OFF + aRow[mi] + (((aseg ^ aXor[mi])) << 4);
                ldsm4(ah[mi][0], ah[mi][1], ah[mi][2], ah[mi][3], ad);
                ad = sb + AL_OFF + aRow[mi] + (((aseg ^ aXor[mi])) << 4);
                ldsm4(al[mi][0], al[mi][1], al[mi][2], al[mi][3], ad);
            }
#pragma unroll
            for (int nt = 0; nt < 4; nt++) {
                uint32_t bd = sb + BH_OFF + bRow[nt] + (((bseg ^ bXor[nt])) << 4);
                ldsm4(bb[nt * 2][0], bb[nt * 2][1], bb[nt * 2 + 1][0], bb[nt * 2 + 1][1], bd);
            }
#pragma unroll
            for (int mi = 0; mi < 2; mi++)
#pragma unroll
                for (int nj = 0; nj < 8; nj++) mma_bf16(acc[mi][nj], ah[mi], bb[nj]);
#pragma unroll
            for (int mi = 0; mi < 2; mi++)
#pragma unroll
                for (int nj = 0; nj < 8; nj++) mma_bf16(acc[mi][nj], al[mi], bb[nj]);
#pragma unroll
            for (int nt = 0; nt < 4; nt++) {
                uint32_t bd = sb + BL_OFF + bRow[nt] + (((bseg ^ bXor[nt])) << 4);
                ldsm4(bb[nt * 2][0], bb[nt * 2][1], bb[nt * 2 + 1][0], bb[nt * 2 + 1][1], bd);
            }
#pragma unroll
            for (int mi = 0; mi < 2; mi++)
#pragma unroll
                for (int nj = 0; nj < 8; nj++) mma_bf16(acc[mi][nj], ah[mi], bb[nj]);
#pragma unroll
            for (int mi = 0; mi < 2; mi++)
#pragma unroll
                for (int nj = 0; nj < 8; nj++) mma_bf16(acc[mi][nj], al[mi], bb[nj]);
        }
    }

    const int grp = lane >> 2, qd = lane & 3;
#pragma unroll
    for (int mi = 0; mi < 2; mi++) {
        int m0r = m0 + wm * 32 + mi * 16 + grp;
        int m1r = m0r + 8;
        int d0v = m0r >> 5, b0v = m0r & 31;
        int d1v = m1r >> 5, b1v = m1r & 31;
        size_t r0 = ((size_t)b0v * DEC_LEN + d0v) * HID;
        size_t r1 = ((size_t)b1v * DEC_LEN + d1v) * HID;
#pragma unroll
        for (int nj = 0; nj < 8; nj++) {
            int cl = n0 + wn * 64 + nj * 8 + qd * 2;
            uint32_t lo;
            uint32_t hi = bf16_split2(acc[mi][nj][0], acc[mi][nj][1], lo);
            *reinterpret_cast<uint32_t*>(&g_pHi[r0 + cl]) = hi;
            *reinterpret_cast<uint32_t*>(&g_pLo[r0 + cl]) = lo;
            hi = bf16_split2(acc[mi][nj][2], acc[mi][nj][3], lo);
            *reinterpret_cast<uint32_t*>(&g_pHi[r1 + cl]) = hi;
            *reinterpret_cast<uint32_t*>(&g_pLo[r1 + cl]) = lo;
        }
    }
}

// =====================================================================
// Kernel 2: score via mma.sync bf16 split-3 (hh + hl + lh), monolithic
// =====================================================================
__global__ __launch_bounds__(256, 2)
void k_score_mma(const int* __restrict__ mask, float* __restrict__ wout) {
    extern __shared__ char dynsmem[];
    __shared__ int mk[128];
    const int tid = threadIdx.x;
    const int wid = tid >> 5, lane = tid & 31;
    const int wm = wid & 3;
    const int wn = wid >> 2;
    const int b = blockIdx.z;
    const int d0 = blockIdx.y * 128;
    const int s0 = blockIdx.x * 128;

    uint32_t buf = (smem_u32(dynsmem) + 1023u) & ~1023u;

    if (tid < 128) mk[tid] = mask[(size_t)(s0 + tid) * BATCH + b];

    const __nv_bfloat16* Ah = g_pHi + ((size_t)b * DEC_LEN + d0) * HID;
    const __nv_bfloat16* Al = g_pLo + ((size_t)b * DEC_LEN + d0) * HID;
    const __nv_bfloat16* Bh = g_eHi + ((size_t)b * ENC_LEN + s0) * HID;
    const __nv_bfloat16* Bl = g_eLo + ((size_t)b * ENC_LEN + s0) * HID;

    auto load_stage = [&](int c, int slot) {
        uint32_t sb = buf + slot * STAGE_BYTES;
        int kofs = c * 32;
#pragma unroll
        for (int i = 0; i < 2; i++) {
            int id = tid + i * 256;
            int row = id >> 2, seg = id & 3;
            uint32_t so = (uint32_t)(row * 64 + ((seg ^ ((row >> 1) & 3)) << 4));
            size_t go = (size_t)row * HID + kofs + seg * 8;
            cp_async16(sb + AH_OFF + so, Ah + go);
            cp_async16(sb + AL_OFF + so, Al + go);
            cp_async16(sb + BH_OFF + so, Bh + go);
            cp_async16(sb + BL_OFF + so, Bl + go);
        }
        cp_commit();
    };

    float acc[2][8][4];
#pragma unroll
    for (int mi = 0; mi < 2; mi++)
#pragma unroll
        for (int nj = 0; nj < 8; nj++)
#pragma unroll
            for (int r = 0; r < 4; r++) acc[mi][nj][r] = 0.f;

    uint32_t aRow[2], aXor[2];
#pragma unroll
    for (int mi = 0; mi < 2; mi++) {
        int r = wm * 32 + mi * 16 + (lane & 15);
        aRow[mi] = (uint32_t)(r * 64);
        aXor[mi] = (uint32_t)((r >> 1) & 3);
    }
    uint32_t bRow[4], bXor[4];
#pragma unroll
    for (int nt = 0; nt < 4; nt++) {
        int r = wn * 64 + nt * 16 + (lane & 7) + ((lane >> 4) << 3);
        bRow[nt] = (uint32_t)(r * 64);
        bXor[nt] = (uint32_t)((r >> 1) & 3);
    }
    const uint32_t aSegBase = (uint32_t)(lane >> 4);
    const uint32_t bSegBase = (uint32_t)((lane >> 3) & 1);

    load_stage(0, 0);
    load_stage(1, 1);

    for (int c = 0; c < 8; c++) {
        if (c < 7) cp_wait<1>(); else cp_wait<0>();
        __syncthreads();                      // chunk c-1 consumers done
        if (c + 2 < 8) load_stage(c + 2, (c + 2) % 3);   // reuse released slot
        uint32_t sb = buf + (c % 3) * STAGE_BYTES;
#pragma unroll
        for (int ks = 0; ks < 2; ks++) {
            uint32_t ah[2][4], al[2][4], bb[8][2];
            uint32_t aseg = (uint32_t)(ks * 2) + aSegBase;
            uint32_t bseg = (uint32_t)(ks * 2) + bSegBase;
#pragma unroll
            for (int mi = 0; mi < 2; mi++) {
                uint32_t ad = sb + AH_OFF + aRow[mi] + (((aseg ^ aXor[mi])) << 4);
                ldsm4(ah[mi][0], ah[mi][1], ah[mi][2], ah[mi][3], ad);
                ad = sb + AL_OFF + aRow[mi] + (((aseg ^ aXor[mi])) << 4);
                ldsm4(al[mi][0], al[mi][1], al[mi][2], al[mi][3], ad);
            }
#pragma unroll
            for (int nt = 0; nt < 4; nt++) {
                uint32_t bd = sb + BH_OFF + bRow[nt] + (((bseg ^ bXor[nt])) << 4);
                ldsm4(bb[nt * 2][0], bb[nt * 2][1], bb[nt * 2 + 1][0], bb[nt * 2 + 1][1], bd);
            }
#pragma unroll
            for (int mi = 0; mi < 2; mi++)
#pragma unroll
                for (int nj = 0; nj < 8; nj++) mma_bf16(acc[mi][nj], ah[mi], bb[nj]);
#pragma unroll
            for (int mi = 0; mi < 2; mi++)
#pragma unroll
                for (int nj = 0; nj < 8; nj++) mma_bf16(acc[mi][nj], al[mi], bb[nj]);
#pragma unroll
            for (int nt = 0; nt < 4; nt++) {
                uint32_t bd = sb + BL_OFF + bRow[nt] + (((bseg ^ bXor[nt])) << 4);
                ldsm4(bb[nt * 2][0], bb[nt * 2][1], bb[nt * 2 + 1][0], bb[nt * 2 + 1][1], bd);
            }
#pragma unroll
            for (int mi = 0; mi < 2; mi++)
#pragma unroll
                for (int nj = 0; nj < 8; nj++) mma_bf16(acc[mi][nj], ah[mi], bb[nj]);
        }
    }

    const int grp = lane >> 2, qd = lane & 3;
#pragma unroll
    for (int mi = 0; mi < 2; mi++) {
        int dr0 = d0 + wm * 32 + mi * 16 + grp;
        int dr1 = dr0 + 8;
        size_t row0 = ((size_t)b * DEC_LEN + dr0) * (size_t)ENC_LEN;
        size_t row1 = ((size_t)b * DEC_LEN + dr1) * (size_t)ENC_LEN;
#pragma unroll
        for (int nj = 0; nj < 8; nj++) {
            int cl = wn * 64 + nj * 8 + qd * 2;
            int m0v = mk[cl], m1v = mk[cl + 1];
            int s = s0 + cl;
            float2 v0, v1;
            v0.x = m0v ? acc[mi][nj][0] : NEGVAL;
            v0.y = m1v ? acc[mi][nj][1] : NEGVAL;
            v1.x = m0v ? acc[mi][nj][2] : NEGVAL;
            v1.y = m1v ? acc[mi][nj][3] : NEGVAL;
            *reinterpret_cast<float2*>(&wout[row0 + s]) = v0;
            *reinterpret_cast<float2*>(&wout[row1 + s]) = v1;
        }
    }
}

// =====================================================================
// Kernel 3: softmax + sparse attn (significant-only __expf)
// =====================================================================
__global__ __launch_bounds__(256)
void k_softmax_attn(const float* __restrict__ enc, float* __restrict__ wts,
                    float* __restrict__ attn) {
    const int r = blockIdx.x;
    const int b = r >> 9;
    const int d = r & 511;
    float* row = wts + (size_t)r * ENC_LEN;
    const int tid = threadIdx.x;
    const int lane = tid & 31, warp = tid >> 5;

    float4 v0 = *reinterpret_cast<const float4*>(&row[tid * 8]);
    float4 v1 = *reinterpret_cast<const float4*>(&row[tid * 8 + 4]);
    float va[8] = {v0.x, v0.y, v0.z, v0.w, v1.x, v1.y, v1.z, v1.w};

    __shared__ float redm[8];
    __shared__ float reds[8];
    __shared__ int cnt;
    __shared__ int sidx[256];
    __shared__ float sw[256];
    if (tid == 0) cnt = 0;

    float m = va[0];
#pragma unroll
    for (int j = 1; j < 8; j++) m = fmaxf(m, va[j]);
#pragma unroll
    for (int o = 16; o; o >>= 1) m = fmaxf(m, __shfl_xor_sync(0xffffffffu, m, o));
    if (lane == 0) redm[warp] = m;
    __syncthreads();
    if (tid < 32) {
        float t = (lane < 8) ? redm[lane] : -3.4e38f;
#pragma unroll
        for (int o = 4; o; o >>= 1) t = fmaxf(t, __shfl_xor_sync(0xffffffffu, t, o));
        if (lane == 0) redm[0] = t;
    }
    __syncthreads();
    const float mx = redm[0];

    float e[8];
    float s = 0.f;
#pragma unroll
    for (int j = 0; j < 8; j++) {
        float x = va[j] - mx;
        e[j] = (x > -30.0f) ? __expf(x) : 0.f;
        s += e[j];
    }
#pragma unroll
    for (int o = 16; o; o >>= 1) s += __shfl_xor_sync(0xffffffffu, s, o);
    if (lane == 0) reds[warp] = s;
    __syncthreads();
    if (tid < 32) {
        float t = (lane < 8) ? reds[lane] : 0.f;
#pragma unroll
        for (int o = 4; o; o >>= 1) t += __shfl_xor_sync(0xffffffffu, t, o);
        if (lane == 0) reds[0] = t;
    }
    __syncthreads();
    const float inv = 1.0f / reds[0];

    float w[8];
#pragma unroll
    for (int j = 0; j < 8; j++) {
        w[j] = e[j] * inv;
        if (e[j] > 0.f) {
            int p = atomicAdd(&cnt, 1);
            if (p < 256) { sidx[p] = tid * 8 + j; sw[p] = w[j]; }
        }
    }
    float4 o0 = make_float4(w[0], w[1], w[2], w[3]);
    float4 o1 = make_float4(w[4], w[5], w[6], w[7]);
    *reinterpret_cast<float4*>(&row[tid * 8]) = o0;
    *reinterpret_cast<float4*>(&row[tid * 8 + 4]) = o1;
    __syncthreads();

    int n = cnt; if (n > 256) n = 256;
    float a = 0.f;
    for (int i = 0; i < n; i++) {
        a += sw[i] * enc[((size_t)sidx[i] * BATCH + b) * HID + tid];
    }
    attn[((size_t)d * BATCH + b) * HID + tid] = a;
}

// =====================================================================
extern "C" void kernel_launch(void* const* d_in, const int* in_sizes, int n_in,
                              void* d_out, int out_size) {
    const float* enc = (const float*)d_in[0];   // (2048, 32, 256)
    const float* dec = (const float*)d_in[1];   // (512, 32, 256)
    const float* W   = (const float*)d_in[2];   // (256, 256)
    const int* mask  = (const int*)d_in[3];     // (2048, 32)

    float* attn = (float*)d_out;
    float* wts  = (float*)d_out + (size_t)DEC_LEN * BATCH * HID;

    static bool attr_done = false;
    if (!attr_done) {
        cudaFuncSetAttribute(k_score_mma, cudaFuncAttributeMaxDynamicSharedMemorySize, SMEM_TOTAL);
        cudaFuncSetAttribute(k_proj_mma, cudaFuncAttributeMaxDynamicSharedMemorySize, SMEM_TOTAL);
        attr_done = true;
    }

    k_prep_enc<<<(ENC_LEN * BATCH * HID / 4) / 256, 256>>>(enc);
    k_prep_decw<<<NDEC_BLOCKS + HID, 256>>>(dec, W);
    k_proj_mma<<<dim3(HID / 128, (DEC_LEN * BATCH) / 128), 256, SMEM_TOTAL>>>();
    k_score_mma<<<dim3(ENC_LEN / 128, DEC_LEN / 128, BATCH), 256, SMEM_TOTAL>>>(mask, wts);
    k_softmax_attn<<<BATCH * DEC_LEN, 256>>>(enc, wts, attn);
}

// round 12
// speedup vs baseline: 1.0547x; 1.0015x over previous
#include <cuda_runtime.h>
#include <cuda_bf16.h>
#include <cstdint>
#include <math.h>

#define ENC_LEN 2048
#define DEC_LEN 512
#define BATCH   32
#define HID     256
#define NEGVAL  (-1.0e12f)

// ---------------- static device scratch (allocation-free) ----------------
__device__ __align__(256) __nv_bfloat16 g_pHi[(size_t)BATCH * DEC_LEN * HID];  // proj hi [b][d][k]
__device__ __align__(256) __nv_bfloat16 g_pLo[(size_t)BATCH * DEC_LEN * HID];  // proj lo
__device__ __align__(256) __nv_bfloat16 g_eHi[(size_t)BATCH * ENC_LEN * HID];  // enc hi  [b][s][k]
__device__ __align__(256) __nv_bfloat16 g_eLo[(size_t)BATCH * ENC_LEN * HID];  // enc lo
__device__ __align__(256) __nv_bfloat16 g_dHi[(size_t)DEC_LEN * BATCH * HID];  // dec hi  [m][k]
__device__ __align__(256) __nv_bfloat16 g_dLo[(size_t)DEC_LEN * BATCH * HID];  // dec lo
__device__ __align__(256) __nv_bfloat16 g_wHi[(size_t)HID * HID];              // W^T hi [n][k]
__device__ __align__(256) __nv_bfloat16 g_wLo[(size_t)HID * HID];              // W^T lo

// ---------------- helpers ----------------
__device__ __forceinline__ uint32_t smem_u32(const void* p) {
    uint32_t a;
    asm("{ .reg .u64 t; cvta.to.shared.u64 t, %1; cvt.u32.u64 %0, t; }" : "=r"(a) : "l"(p));
    return a;
}
__device__ __forceinline__ void cp_async16(uint32_t saddr, const void* gaddr) {
    asm volatile("cp.async.cg.shared.global [%0], [%1], 16;" :: "r"(saddr), "l"(gaddr) : "memory");
}
__device__ __forceinline__ void cp_commit() { asm volatile("cp.async.commit_group;" ::: "memory"); }
template <int N>
__device__ __forceinline__ void cp_wait() { asm volatile("cp.async.wait_group %0;" :: "n"(N) : "memory"); }

__device__ __forceinline__ void ldsm4(uint32_t& r0, uint32_t& r1, uint32_t& r2, uint32_t& r3, uint32_t addr) {
    asm volatile("ldmatrix.sync.aligned.m8n8.x4.shared.b16 {%0,%1,%2,%3}, [%4];"
                 : "=r"(r0), "=r"(r1), "=r"(r2), "=r"(r3) : "r"(addr));
}
__device__ __forceinline__ void mma_bf16(float* c, const uint32_t* a, const uint32_t* b) {
    asm volatile(
        "mma.sync.aligned.m16n8k16.row.col.f32.bf16.bf16.f32 "
        "{%0,%1,%2,%3}, {%4,%5,%6,%7}, {%8,%9}, {%0,%1,%2,%3};"
        : "+f"(c[0]), "+f"(c[1]), "+f"(c[2]), "+f"(c[3])
        : "r"(a[0]), "r"(a[1]), "r"(a[2]), "r"(a[3]), "r"(b[0]), "r"(b[1]));
}

__device__ __forceinline__ void bf16_split4(float4 v, uint2& hi, uint2& lo) {
    __nv_bfloat16 hx = __float2bfloat16_rn(v.x), hy = __float2bfloat16_rn(v.y);
    __nv_bfloat16 hz = __float2bfloat16_rn(v.z), hw = __float2bfloat16_rn(v.w);
    __nv_bfloat16 lx = __float2bfloat16_rn(v.x - __bfloat162float(hx));
    __nv_bfloat16 ly = __float2bfloat16_rn(v.y - __bfloat162float(hy));
    __nv_bfloat16 lz = __float2bfloat16_rn(v.z - __bfloat162float(hz));
    __nv_bfloat16 lw = __float2bfloat16_rn(v.w - __bfloat162float(hw));
    __nv_bfloat162 h01 = __halves2bfloat162(hx, hy), h23 = __halves2bfloat162(hz, hw);
    __nv_bfloat162 l01 = __halves2bfloat162(lx, ly), l23 = __halves2bfloat162(lz, lw);
    hi.x = *reinterpret_cast<uint32_t*>(&h01); hi.y = *reinterpret_cast<uint32_t*>(&h23);
    lo.x = *reinterpret_cast<uint32_t*>(&l01); lo.y = *reinterpret_cast<uint32_t*>(&l23);
}
__device__ __forceinline__ uint32_t bf16_split2(float a, float b, uint32_t& lo) {
    __nv_bfloat16 ha = __float2bfloat16_rn(a), hb = __float2bfloat16_rn(b);
    __nv_bfloat16 la = __float2bfloat16_rn(a - __bfloat162float(ha));
    __nv_bfloat16 lb = __float2bfloat16_rn(b - __bfloat162float(hb));
    __nv_bfloat162 h = __halves2bfloat162(ha, hb), l = __halves2bfloat162(la, lb);
    lo = *reinterpret_cast<uint32_t*>(&l);
    return *reinterpret_cast<uint32_t*>(&h);
}

// =====================================================================
// Kernel 0a: enc (s,b,h) f32 -> bf16 hi/lo [b][s][h]
// =====================================================================
__global__ __launch_bounds__(256)
void k_prep_enc(const float* __restrict__ enc) {
    size_t fid = (size_t)blockIdx.x * 256 + threadIdx.x;
    int h4 = (int)(fid & 63);
    int sb = (int)(fid >> 6);
    int b = sb & 31;
    int s = sb >> 5;
    float4 v = reinterpret_cast<const float4*>(enc)[fid];
    uint2 hi, lo;
    bf16_split4(v, hi, lo);
    size_t o = ((size_t)b * ENC_LEN + s) * 64 + h4;
    reinterpret_cast<uint2*>(g_eHi)[o] = hi;
    reinterpret_cast<uint2*>(g_eLo)[o] = lo;
}

// =====================================================================
// Kernel 0b: fused dec split + W transpose/split
// =====================================================================
#define NDEC_BLOCKS ((DEC_LEN * BATCH * HID / 4) / 256)
__global__ __launch_bounds__(256)
void k_prep_decw(const float* __restrict__ dec, const float* __restrict__ W) {
    if (blockIdx.x < NDEC_BLOCKS) {
        size_t fid = (size_t)blockIdx.x * 256 + threadIdx.x;
        float4 v = reinterpret_cast<const float4*>(dec)[fid];
        uint2 hi, lo;
        bf16_split4(v, hi, lo);
        reinterpret_cast<uint2*>(g_dHi)[fid] = hi;
        reinterpret_cast<uint2*>(g_dLo)[fid] = lo;
    } else {
        int n = blockIdx.x - NDEC_BLOCKS;
        int k = threadIdx.x;
        float v = W[(size_t)k * HID + n];
        __nv_bfloat16 h = __float2bfloat16_rn(v);
        __nv_bfloat16 l = __float2bfloat16_rn(v - __bfloat162float(h));
        g_wHi[(size_t)n * HID + k] = h;
        g_wLo[(size_t)n * HID + k] = l;
    }
}

// =====================================================================
// tile machinery: CTA tile 128(m) x 128(n), K chunks of 32 (64B rows),
// 3-stage cp.async pipeline, single barrier per chunk.
// ks-step order staggered by warp parity; ldsm reordered so only
// (ah, bh) precede the first mma pass — al/bl hide under mma passes.
// =====================================================================
#define STAGE_BYTES 32768
#define AH_OFF 0
#define AL_OFF 8192
#define BH_OFF 16384
#define BL_OFF 24576
#define SMEM_TOTAL (3 * STAGE_BYTES + 1024)

// =====================================================================
// Kernel 1: proj = dec @ W^T(T) via bf16 split-4 (hh+lh+hl+ll) MMA
// =====================================================================
__global__ __launch_bounds__(256, 2)
void k_proj_mma() {
    extern __shared__ char dynsmem[];
    const int tid = threadIdx.x;
    const int wid = tid >> 5, lane = tid & 31;
    const int wm = wid & 3;
    const int wn = wid >> 2;
    const int n0 = blockIdx.x * 128;
    const int m0 = blockIdx.y * 128;

    uint32_t buf = (smem_u32(dynsmem) + 1023u) & ~1023u;

    const __nv_bfloat16* Ah = g_dHi + (size_t)m0 * HID;
    const __nv_bfloat16* Al = g_dLo + (size_t)m0 * HID;
    const __nv_bfloat16* Bh = g_wHi + (size_t)n0 * HID;
    const __nv_bfloat16* Bl = g_wLo + (size_t)n0 * HID;

    auto load_stage = [&](int c, int slot) {
        uint32_t sb = buf + slot * STAGE_BYTES;
        int kofs = c * 32;
#pragma unroll
        for (int i = 0; i < 2; i++) {
            int id = tid + i * 256;
            int row = id >> 2, seg = id & 3;
            uint32_t so = (uint32_t)(row * 64 + ((seg ^ ((row >> 1) & 3)) << 4));
            size_t go = (size_t)row * HID + kofs + seg * 8;
            cp_async16(sb + AH_OFF + so, Ah + go);
            cp_async16(sb + AL_OFF + so, Al + go);
            cp_async16(sb + BH_OFF + so, Bh + go);
            cp_async16(sb + BL_OFF + so, Bl + go);
        }
        cp_commit();
    };

    float acc[2][8][4];
#pragma unroll
    for (int mi = 0; mi < 2; mi++)
#pragma unroll
        for (int nj = 0; nj < 8; nj++)
#pragma unroll
            for (int r = 0; r < 4; r++) acc[mi][nj][r] = 0.f;

    uint32_t aRow[2], aXor[2];
#pragma unroll
    for (int mi = 0; mi < 2; mi++) {
        int r = wm * 32 + mi * 16 + (lane & 15);
        aRow[mi] = (uint32_t)(r * 64);
        aXor[mi] = (uint32_t)((r >> 1) & 3);
    }
    uint32_t bRow[4], bXor[4];
#pragma unroll
    for (int nt = 0; nt < 4; nt++) {
        int r = wn * 64 + nt * 16 + (lane & 7) + ((lane >> 4) << 3);
        bRow[nt] = (uint32_t)(r * 64);
        bXor[nt] = (uint32_t)((r >> 1) & 3);
    }
    const uint32_t aSegBase = (uint32_t)(lane >> 4);
    const uint32_t bSegBase = (uint32_t)((lane >> 3) & 1);
    const int ksFlip = wid & 1;   // stagger ks order across warps

    load_stage(0, 0);
    load_stage(1, 1);

    for (int c = 0; c < 8; c++) {
        if (c < 7) cp_wait<1>(); else cp_wait<0>();
        __syncthreads();
        if (c + 2 < 8) load_stage(c + 2, (c + 2) % 3);
        uint32_t sb = buf + (c % 3) * STAGE_BYTES;
#pragma unroll
        for (int ksi = 0; ksi < 2; ksi++) {
            int ks = ksFlip ? (1 - ksi) : ksi;
            uint32_t ah[2][4], al[2][4], bb[8][2];
            uint32_t aseg = (uint32_t)(ks * 2) + aSegBase;
            uint32_t bseg = (uint32_t)(ks * 2) + bSegBase;
            // minimal prefix: ah + bh only
#pragma unroll
            for (int mi = 0; mi < 2; mi++) {
                uint32_t ad = sb + AH_OFF + aRow[mi] + (((aseg ^ aXor[mi])) << 4);
                ldsm4(ah[mi][0], ah[mi][1], ah[mi][2], ah[mi][3], ad);
            }
#pragma unroll
            for (int nt = 0; nt < 4; nt++) {
                uint32_t bd = sb + BH_OFF + bRow[nt] + (((bseg ^ bXor[nt])) << 4);
                ldsm4(bb[nt * 2][0], bb[nt * 2][1], bb[nt * 2 + 1][0], bb[nt * 2 + 1][1], bd);
            }
            // pass 1: ah*bh
#pragma unroll
            for (int mi = 0; mi < 2; mi++)
#pragma unroll
                for (int nj = 0; nj < 8; nj++) mma_bf16(acc[mi][nj], ah[mi], bb[nj]);
            // al hides under pass 1
#pragma unroll
            for (int mi = 0; mi < 2; mi++) {
                uint32_t ad = sb + AL_OFF + aRow[mi] + (((aseg ^ aXor[mi])) << 4);
                ldsm4(al[mi][0], al[mi][1], al[mi][2], al[mi][3], ad);
            }
            // pass 2: al*bh
#pragma unroll
            for (int mi = 0; mi < 2; mi++)
#pragma unroll
                for (int nj = 0; nj < 8; nj++) mma_bf16(acc[mi][nj], al[mi], bb[nj]);
            // bl hides under pass 2
#pragma unroll
            for (int nt = 0; nt < 4; nt++) {
                uint32_t bd = sb + BL_OFF + bRow[nt] + (((bseg ^ bXor[nt])) << 4);
                ldsm4(bb[nt * 2][0], bb[nt * 2][1], bb[nt * 2 + 1][0], bb[nt * 2 + 1][1], bd);
            }
            // pass 3: ah*bl
#pragma unroll
            for (int mi = 0; mi < 2; mi++)
#pragma unroll
                for (int nj = 0; nj < 8; nj++) mma_bf16(acc[mi][nj], ah[mi], bb[nj]);
            // pass 4: al*bl
#pragma unroll
            for (int mi = 0; mi < 2; mi++)
#pragma unroll
                for (int nj = 0; nj < 8; nj++) mma_bf16(acc[mi][nj], al[mi], bb[nj]);
        }
    }

    const int grp = lane >> 2, qd = lane & 3;
#pragma unroll
    for (int mi = 0; mi < 2; mi++) {
        int m0r = m0 + wm * 32 + mi * 16 + grp;
        int m1r = m0r + 8;
        int d0v = m0r >> 5, b0v = m0r & 31;
        int d1v = m1r >> 5, b1v = m1r & 31;
        size_t r0 = ((size_t)b0v * DEC_LEN + d0v) * HID;
        size_t r1 = ((size_t)b1v * DEC_LEN + d1v) * HID;
#pragma unroll
        for (int nj = 0; nj < 8; nj++) {
            int cl = n0 + wn * 64 + nj * 8 + qd * 2;
            uint32_t lo;
            uint32_t hi = bf16_split2(acc[mi][nj][0], acc[mi][nj][1], lo);
            *reinterpret_cast<uint32_t*>(&g_pHi[r0 + cl]) = hi;
            *reinterpret_cast<uint32_t*>(&g_pLo[r0 + cl]) = lo;
            hi = bf16_split2(acc[mi][nj][2], acc[mi][nj][3], lo);
            *reinterpret_cast<uint32_t*>(&g_pHi[r1 + cl]) = hi;
            *reinterpret_cast<uint32_t*>(&g_pLo[r1 + cl]) = lo;
        }
    }
}

// =====================================================================
// Kernel 2: score via mma.sync bf16 split-3 (hh + lh + hl), monolithic
// =====================================================================
__global__ __launch_bounds__(256, 2)
void k_score_mma(const int* __restrict__ mask, float* __restrict__ wout) {
    extern __shared__ char dynsmem[];
    __shared__ int mk[128];
    const int tid = threadIdx.x;
    const int wid = tid >> 5, lane = tid & 31;
    const int wm = wid & 3;
    const int wn = wid >> 2;
    const int b = blockIdx.z;
    const int d0 = blockIdx.y * 128;
    const int s0 = blockIdx.x * 128;

    uint32_t buf = (smem_u32(dynsmem) + 1023u) & ~1023u;

    if (tid < 128) mk[tid] = mask[(size_t)(s0 + tid) * BATCH + b];

    const __nv_bfloat16* Ah = g_pHi + ((size_t)b * DEC_LEN + d0) * HID;
    const __nv_bfloat16* Al = g_pLo + ((size_t)b * DEC_LEN + d0) * HID;
    const __nv_bfloat16* Bh = g_eHi + ((size_t)b * ENC_LEN + s0) * HID;
    const __nv_bfloat16* Bl = g_eLo + ((size_t)b * ENC_LEN + s0) * HID;

    auto load_stage = [&](int c, int slot) {
        uint32_t sb = buf + slot * STAGE_BYTES;
        int kofs = c * 32;
#pragma unroll
        for (int i = 0; i < 2; i++) {
            int id = tid + i * 256;
            int row = id >> 2, seg = id & 3;
            uint32_t so = (uint32_t)(row * 64 + ((seg ^ ((row >> 1) & 3)) << 4));
            size_t go = (size_t)row * HID + kofs + seg * 8;
            cp_async16(sb + AH_OFF + so, Ah + go);
            cp_async16(sb + AL_OFF + so, Al + go);
            cp_async16(sb + BH_OFF + so, Bh + go);
            cp_async16(sb + BL_OFF + so, Bl + go);
        }
        cp_commit();
    };

    float acc[2][8][4];
#pragma unroll
    for (int mi = 0; mi < 2; mi++)
#pragma unroll
        for (int nj = 0; nj < 8; nj++)
#pragma unroll
            for (int r = 0; r < 4; r++) acc[mi][nj][r] = 0.f;

    uint32_t aRow[2], aXor[2];
#pragma unroll
    for (int mi = 0; mi < 2; mi++) {
        int r = wm * 32 + mi * 16 + (lane & 15);
        aRow[mi] = (uint32_t)(r * 64);
        aXor[mi] = (uint32_t)((r >> 1) & 3);
    }
    uint32_t bRow[4], bXor[4];
#pragma unroll
    for (int nt = 0; nt < 4; nt++) {
        int r = wn * 64 + nt * 16 + (lane & 7) + ((lane >> 4) << 3);
        bRow[nt] = (uint32_t)(r * 64);
        bXor[nt] = (uint32_t)((r >> 1) & 3);
    }
    const uint32_t aSegBase = (uint32_t)(lane >> 4);
    const uint32_t bSegBase = (uint32_t)((lane >> 3) & 1);
    const int ksFlip = wid & 1;   // stagger ks order across warps

    load_stage(0, 0);
    load_stage(1, 1);

    for (int c = 0; c < 8; c++) {
        if (c < 7) cp_wait<1>(); else cp_wait<0>();
        __syncthreads();
        if (c + 2 < 8) load_stage(c + 2, (c + 2) % 3);
        uint32_t sb = buf + (c % 3) * STAGE_BYTES;
#pragma unroll
        for (int ksi = 0; ksi < 2; ksi++) {
            int ks = ksFlip ? (1 - ksi) : ksi;
            uint32_t ah[2][4], al[2][4], bb[8][2];
            uint32_t aseg = (uint32_t)(ks * 2) + aSegBase;
            uint32_t bseg = (uint32_t)(ks * 2) + bSegBase;
            // minimal prefix: ah + bh only
#pragma unroll
            for (int mi = 0; mi < 2; mi++) {
                uint32_t ad = sb + AH_OFF + aRow[mi] + (((aseg ^ aXor[mi])) << 4);
                ldsm4(ah[mi][0], ah[mi][1], ah[mi][2], ah[mi][3], ad);
            }
#pragma unroll
            for (int nt = 0; nt < 4; nt++) {
                uint32_t bd = sb + BH_OFF + bRow[nt] + (((bseg ^ bXor[nt])) << 4);
                ldsm4(bb[nt * 2][0], bb[nt * 2][1], bb[nt * 2 + 1][0], bb[nt * 2 + 1][1], bd);
            }
            // pass 1: ah*bh
#pragma unroll
            for (int mi = 0; mi < 2; mi++)
#pragma unroll
                for (int nj = 0; nj < 8; nj++) mma_bf16(acc[mi][nj], ah[mi], bb[nj]);
            // al hides under pass 1
#pragma unroll
            for (int mi = 0; mi < 2; mi++) {
                uint32_t ad = sb + AL_OFF + aRow[mi] + (((aseg ^ aXor[mi])) << 4);
                ldsm4(al[mi][0], al[mi][1], al[mi][2], al[mi][3], ad);
            }
            // pass 2: al*bh
#pragma unroll
            for (int mi = 0; mi < 2; mi++)
#pragma unroll
                for (int nj = 0; nj < 8; nj++) mma_bf16(acc[mi][nj], al[mi], bb[nj]);
            // bl hides under pass 2
#pragma unroll
            for (int nt = 0; nt < 4; nt++) {
                uint32_t bd = sb + BL_OFF + bRow[nt] + (((bseg ^ bXor[nt])) << 4);
                ldsm4(bb[nt * 2][0], bb[nt * 2][1], bb[nt * 2 + 1][0], bb[nt * 2 + 1][1], bd);
            }
            // pass 3: ah*bl
#pragma unroll
            for (int mi = 0; mi < 2; mi++)
#pragma unroll
                for (int nj = 0; nj < 8; nj++) mma_bf16(acc[mi][nj], ah[mi], bb[nj]);
        }
    }

    const int grp = lane >> 2, qd = lane & 3;
#pragma unroll
    for (int mi = 0; mi < 2; mi++) {
        int dr0 = d0 + wm * 32 + mi * 16 + grp;
        int dr1 = dr0 + 8;
        size_t row0 = ((size_t)b * DEC_LEN + dr0) * (size_t)ENC_LEN;
        size_t row1 = ((size_t)b * DEC_LEN + dr1) * (size_t)ENC_LEN;
#pragma unroll
        for (int nj = 0; nj < 8; nj++) {
            int cl = wn * 64 + nj * 8 + qd * 2;
            int m0v = mk[cl], m1v = mk[cl + 1];
            int s = s0 + cl;
            float2 v0, v1;
            v0.x = m0v ? acc[mi][nj][0] : NEGVAL;
            v0.y = m1v ? acc[mi][nj][1] : NEGVAL;
            v1.x = m0v ? acc[mi][nj][2] : NEGVAL;
            v1.y = m1v ? acc[mi][nj][3] : NEGVAL;
            *reinterpret_cast<float2*>(&wout[row0 + s]) = v0;
            *reinterpret_cast<float2*>(&wout[row1 + s]) = v1;
        }
    }
}

// =====================================================================
// Kernel 3: softmax + sparse attn (significant-only __expf)
// =====================================================================
__global__ __launch_bounds__(256)
void k_softmax_attn(const float* __restrict__ enc, float* __restrict__ wts,
                    float* __restrict__ attn) {
    const int r = blockIdx.x;
    const int b = r >> 9;
    const int d = r & 511;
    float* row = wts + (size_t)r * ENC_LEN;
    const int tid = threadIdx.x;
    const int lane = tid & 31, warp = tid >> 5;

    float4 v0 = *reinterpret_cast<const float4*>(&row[tid * 8]);
    float4 v1 = *reinterpret_cast<const float4*>(&row[tid * 8 + 4]);
    float va[8] = {v0.x, v0.y, v0.z, v0.w, v1.x, v1.y, v1.z, v1.w};

    __shared__ float redm[8];
    __shared__ float reds[8];
    __shared__ int cnt;
    __shared__ int sidx[256];
    __shared__ float sw[256];
    if (tid == 0) cnt = 0;

    float m = va[0];
#pragma unroll
    for (int j = 1; j < 8; j++) m = fmaxf(m, va[j]);
#pragma unroll
    for (int o = 16; o; o >>= 1) m = fmaxf(m, __shfl_xor_sync(0xffffffffu, m, o));
    if (lane == 0) redm[warp] = m;
    __syncthreads();
    if (tid < 32) {
        float t = (lane < 8) ? redm[lane] : -3.4e38f;
#pragma unroll
        for (int o = 4; o; o >>= 1) t = fmaxf(t, __shfl_xor_sync(0xffffffffu, t, o));
        if (lane == 0) redm[0] = t;
    }
    __syncthreads();
    const float mx = redm[0];

    float e[8];
    float s = 0.f;
#pragma unroll
    for (int j = 0; j < 8; j++) {
        float x = va[j] - mx;
        e[j] = (x > -30.0f) ? __expf(x) : 0.f;
        s += e[j];
    }
#pragma unroll
    for (int o = 16; o; o >>= 1) s += __shfl_xor_sync(0xffffffffu, s, o);
    if (lane == 0) reds[warp] = s;
    __syncthreads();
    if (tid < 32) {
        float t = (lane < 8) ? reds[lane] : 0.f;
#pragma unroll
        for (int o = 4; o; o >>= 1) t += __shfl_xor_sync(0xffffffffu, t, o);
        if (lane == 0) reds[0] = t;
    }
    __syncthreads();
    const float inv = 1.0f / reds[0];

    float w[8];
#pragma unroll
    for (int j = 0; j < 8; j++) {
        w[j] = e[j] * inv;
        if (e[j] > 0.f) {
            int p = atomicAdd(&cnt, 1);
            if (p < 256) { sidx[p] = tid * 8 + j; sw[p] = w[j]; }
        }
    }
    float4 o0 = make_float4(w[0], w[1], w[2], w[3]);
    float4 o1 = make_float4(w[4], w[5], w[6], w[7]);
    *reinterpret_cast<float4*>(&row[tid * 8]) = o0;
    *reinterpret_cast<float4*>(&row[tid * 8 + 4]) = o1;
    __syncthreads();

    int n = cnt; if (n > 256) n = 256;
    float a = 0.f;
    for (int i = 0; i < n; i++) {
        a += sw[i] * enc[((size_t)sidx[i] * BATCH + b) * HID + tid];
    }
    attn[((size_t)d * BATCH + b) * HID + tid] = a;
}

// =====================================================================
extern "C" void kernel_launch(void* const* d_in, const int* in_sizes, int n_in,
                              void* d_out, int out_size) {
    const float* enc = (const float*)d_in[0];   // (2048, 32, 256)
    const float* dec = (const float*)d_in[1];   // (512, 32, 256)
    const float* W   = (const float*)d_in[2];   // (256, 256)
    const int* mask  = (const int*)d_in[3];     // (2048, 32)

    float* attn = (float*)d_out;
    float* wts  = (float*)d_out + (size_t)DEC_LEN * BATCH * HID;

    static bool attr_done = false;
    if (!attr_done) {
        cudaFuncSetAttribute(k_score_mma, cudaFuncAttributeMaxDynamicSharedMemorySize, SMEM_TOTAL);
        cudaFuncSetAttribute(k_proj_mma, cudaFuncAttributeMaxDynamicSharedMemorySize, SMEM_TOTAL);
        attr_done = true;
    }

    k_prep_enc<<<(ENC_LEN * BATCH * HID / 4) / 256, 256>>>(enc);
    k_prep_decw<<<NDEC_BLOCKS + HID, 256>>>(dec, W);
    k_proj_mma<<<dim3(HID / 128, (DEC_LEN * BATCH) / 128), 256, SMEM_TOTAL>>>();
    k_score_mma<<<dim3(ENC_LEN / 128, DEC_LEN / 128, BATCH), 256, SMEM_TOTAL>>>(mask, wts);
    k_softmax_attn<<<BATCH * DEC_LEN, 256>>>(enc, wts, attn);
}

// round 13
// speedup vs baseline: 1.1353x; 1.0764x over previous
#include <cuda_runtime.h>
#include <cuda_bf16.h>
#include <cstdint>
#include <math.h>

#define ENC_LEN 2048
#define DEC_LEN 512
#define BATCH   32
#define HID     256
#define NEGVAL  (-1.0e12f)

// ---------------- static device scratch (allocation-free) ----------------
__device__ __align__(256) __nv_bfloat16 g_pHi[(size_t)BATCH * DEC_LEN * HID];  // proj hi [b][d][k]
__device__ __align__(256) __nv_bfloat16 g_pLo[(size_t)BATCH * DEC_LEN * HID];  // proj lo
__device__ __align__(256) __nv_bfloat16 g_eHi[(size_t)BATCH * ENC_LEN * HID];  // enc hi  [b][j][k] compacted
__device__ __align__(256) __nv_bfloat16 g_eLo[(size_t)BATCH * ENC_LEN * HID];  // enc lo  compacted
__device__ __align__(256) __nv_bfloat16 g_dHi[(size_t)DEC_LEN * BATCH * HID];  // dec hi  [m][k]
__device__ __align__(256) __nv_bfloat16 g_dLo[(size_t)DEC_LEN * BATCH * HID];  // dec lo
__device__ __align__(256) __nv_bfloat16 g_wHi[(size_t)HID * HID];              // W^T hi [n][k]
__device__ __align__(256) __nv_bfloat16 g_wLo[(size_t)HID * HID];              // W^T lo
__device__ int g_cidx[BATCH * ENC_LEN];   // [b][j] -> s
__device__ int g_pos[BATCH * ENC_LEN];    // [b][s] -> j (or -1 if masked)
__device__ int g_nb[BATCH];               // unmasked count per batch

// ---------------- helpers ----------------
__device__ __forceinline__ uint32_t smem_u32(const void* p) {
    uint32_t a;
    asm("{ .reg .u64 t; cvta.to.shared.u64 t, %1; cvt.u32.u64 %0, t; }" : "=r"(a) : "l"(p));
    return a;
}
__device__ __forceinline__ void cp_async16(uint32_t saddr, const void* gaddr) {
    asm volatile("cp.async.cg.shared.global [%0], [%1], 16;" :: "r"(saddr), "l"(gaddr) : "memory");
}
__device__ __forceinline__ void cp_commit() { asm volatile("cp.async.commit_group;" ::: "memory"); }
template <int N>
__device__ __forceinline__ void cp_wait() { asm volatile("cp.async.wait_group %0;" :: "n"(N) : "memory"); }

__device__ __forceinline__ void ldsm4(uint32_t& r0, uint32_t& r1, uint32_t& r2, uint32_t& r3, uint32_t addr) {
    asm volatile("ldmatrix.sync.aligned.m8n8.x4.shared.b16 {%0,%1,%2,%3}, [%4];"
                 : "=r"(r0), "=r"(r1), "=r"(r2), "=r"(r3) : "r"(addr));
}
__device__ __forceinline__ void mma_bf16(float* c, const uint32_t* a, const uint32_t* b) {
    asm volatile(
        "mma.sync.aligned.m16n8k16.row.col.f32.bf16.bf16.f32 "
        "{%0,%1,%2,%3}, {%4,%5,%6,%7}, {%8,%9}, {%0,%1,%2,%3};"
        : "+f"(c[0]), "+f"(c[1]), "+f"(c[2]), "+f"(c[3])
        : "r"(a[0]), "r"(a[1]), "r"(a[2]), "r"(a[3]), "r"(b[0]), "r"(b[1]));
}

__device__ __forceinline__ void bf16_split4(float4 v, uint2& hi, uint2& lo) {
    __nv_bfloat16 hx = __float2bfloat16_rn(v.x), hy = __float2bfloat16_rn(v.y);
    __nv_bfloat16 hz = __float2bfloat16_rn(v.z), hw = __float2bfloat16_rn(v.w);
    __nv_bfloat16 lx = __float2bfloat16_rn(v.x - __bfloat162float(hx));
    __nv_bfloat16 ly = __float2bfloat16_rn(v.y - __bfloat162float(hy));
    __nv_bfloat16 lz = __float2bfloat16_rn(v.z - __bfloat162float(hz));
    __nv_bfloat16 lw = __float2bfloat16_rn(v.w - __bfloat162float(hw));
    __nv_bfloat162 h01 = __halves2bfloat162(hx, hy), h23 = __halves2bfloat162(hz, hw);
    __nv_bfloat162 l01 = __halves2bfloat162(lx, ly), l23 = __halves2bfloat162(lz, lw);
    hi.x = *reinterpret_cast<uint32_t*>(&h01); hi.y = *reinterpret_cast<uint32_t*>(&h23);
    lo.x = *reinterpret_cast<uint32_t*>(&l01); lo.y = *reinterpret_cast<uint32_t*>(&l23);
}
__device__ __forceinline__ uint32_t bf16_split2(float a, float b, uint32_t& lo) {
    __nv_bfloat16 ha = __float2bfloat16_rn(a), hb = __float2bfloat16_rn(b);
    __nv_bfloat16 la = __float2bfloat16_rn(a - __bfloat162float(ha));
    __nv_bfloat16 lb = __float2bfloat16_rn(b - __bfloat162float(hb));
    __nv_bfloat162 h = __halves2bfloat162(ha, hb), l = __halves2bfloat162(la, lb);
    lo = *reinterpret_cast<uint32_t*>(&l);
    return *reinterpret_cast<uint32_t*>(&h);
}

// =====================================================================
// Kernel M: per-batch mask prefix scan -> cidx / pos / nb
// grid = BATCH, block = 256, 8 elements per thread
// =====================================================================
__global__ __launch_bounds__(256)
void k_mask_scan(const int* __restrict__ mask) {
    const int b = blockIdx.x;
    const int t = threadIdx.x;
    __shared__ int sc[256];
    int m[8], cnt = 0;
#pragma unroll
    for (int j = 0; j < 8; j++) {
        int s = t * 8 + j;
        m[j] = mask[(size_t)s * BATCH + b];
        cnt += (m[j] != 0);
    }
    sc[t] = cnt;
    __syncthreads();
    // Hillis-Steele inclusive scan
    for (int off = 1; off < 256; off <<= 1) {
        int v = (t >= off) ? sc[t - off] : 0;
        __syncthreads();
        sc[t] += v;
        __syncthreads();
    }
    int base = sc[t] - cnt;   // exclusive prefix
#pragma unroll
    for (int j = 0; j < 8; j++) {
        int s = t * 8 + j;
        if (m[j] != 0) {
            g_cidx[b * ENC_LEN + base] = s;
            g_pos[b * ENC_LEN + s] = base;
            base++;
        } else {
            g_pos[b * ENC_LEN + s] = -1;
        }
    }
    if (t == 255) g_nb[b] = sc[255];
}

// =====================================================================
// Kernel 0a: enc (s,b,h) f32 -> bf16 hi/lo, COMPACTED rows [b][j][h]
// =====================================================================
__global__ __launch_bounds__(256)
void k_prep_enc(const float* __restrict__ enc) {
    size_t fid = (size_t)blockIdx.x * 256 + threadIdx.x;
    int h4 = (int)(fid & 63);
    int sb = (int)(fid >> 6);
    int b = sb & 31;
    int s = sb >> 5;
    int p = g_pos[b * ENC_LEN + s];
    if (p < 0) return;                       // masked row: dropped
    float4 v = reinterpret_cast<const float4*>(enc)[fid];
    uint2 hi, lo;
    bf16_split4(v, hi, lo);
    size_t o = ((size_t)b * ENC_LEN + p) * 64 + h4;
    reinterpret_cast<uint2*>(g_eHi)[o] = hi;
    reinterpret_cast<uint2*>(g_eLo)[o] = lo;
}

// =====================================================================
// Kernel 0b: fused dec split + W transpose/split
// =====================================================================
#define NDEC_BLOCKS ((DEC_LEN * BATCH * HID / 4) / 256)
__global__ __launch_bounds__(256)
void k_prep_decw(const float* __restrict__ dec, const float* __restrict__ W) {
    if (blockIdx.x < NDEC_BLOCKS) {
        size_t fid = (size_t)blockIdx.x * 256 + threadIdx.x;
        float4 v = reinterpret_cast<const float4*>(dec)[fid];
        uint2 hi, lo;
        bf16_split4(v, hi, lo);
        reinterpret_cast<uint2*>(g_dHi)[fid] = hi;
        reinterpret_cast<uint2*>(g_dLo)[fid] = lo;
    } else {
        int n = blockIdx.x - NDEC_BLOCKS;
        int k = threadIdx.x;
        float v = W[(size_t)k * HID + n];
        __nv_bfloat16 h = __float2bfloat16_rn(v);
        __nv_bfloat16 l = __float2bfloat16_rn(v - __bfloat162float(h));
        g_wHi[(size_t)n * HID + k] = h;
        g_wLo[(size_t)n * HID + k] = l;
    }
}

// =====================================================================
// tile machinery (as round 12, passing)
// =====================================================================
#define STAGE_BYTES 32768
#define AH_OFF 0
#define AL_OFF 8192
#define BH_OFF 16384
#define BL_OFF 24576
#define SMEM_TOTAL (3 * STAGE_BYTES + 1024)

// =====================================================================
// Kernel 1: proj = dec @ W^T(T) via bf16 split-4 MMA (unchanged)
// =====================================================================
__global__ __launch_bounds__(256, 2)
void k_proj_mma() {
    extern __shared__ char dynsmem[];
    const int tid = threadIdx.x;
    const int wid = tid >> 5, lane = tid & 31;
    const int wm = wid & 3;
    const int wn = wid >> 2;
    const int n0 = blockIdx.x * 128;
    const int m0 = blockIdx.y * 128;

    uint32_t buf = (smem_u32(dynsmem) + 1023u) & ~1023u;

    const __nv_bfloat16* Ah = g_dHi + (size_t)m0 * HID;
    const __nv_bfloat16* Al = g_dLo + (size_t)m0 * HID;
    const __nv_bfloat16* Bh = g_wHi + (size_t)n0 * HID;
    const __nv_bfloat16* Bl = g_wLo + (size_t)n0 * HID;

    auto load_stage = [&](int c, int slot) {
        uint32_t sb = buf + slot * STAGE_BYTES;
        int kofs = c * 32;
#pragma unroll
        for (int i = 0; i < 2; i++) {
            int id = tid + i * 256;
            int row = id >> 2, seg = id & 3;
            uint32_t so = (uint32_t)(row * 64 + ((seg ^ ((row >> 1) & 3)) << 4));
            size_t go = (size_t)row * HID + kofs + seg * 8;
            cp_async16(sb + AH_OFF + so, Ah + go);
            cp_async16(sb + AL_OFF + so, Al + go);
            cp_async16(sb + BH_OFF + so, Bh + go);
            cp_async16(sb + BL_OFF + so, Bl + go);
        }
        cp_commit();
    };

    float acc[2][8][4];
#pragma unroll
    for (int mi = 0; mi < 2; mi++)
#pragma unroll
        for (int nj = 0; nj < 8; nj++)
#pragma unroll
            for (int r = 0; r < 4; r++) acc[mi][nj][r] = 0.f;

    uint32_t aRow[2], aXor[2];
#pragma unroll
    for (int mi = 0; mi < 2; mi++) {
        int r = wm * 32 + mi * 16 + (lane & 15);
        aRow[mi] = (uint32_t)(r * 64);
        aXor[mi] = (uint32_t)((r >> 1) & 3);
    }
    uint32_t bRow[4], bXor[4];
#pragma unroll
    for (int nt = 0; nt < 4; nt++) {
        int r = wn * 64 + nt * 16 + (lane & 7) + ((lane >> 4) << 3);
        bRow[nt] = (uint32_t)(r * 64);
        bXor[nt] = (uint32_t)((r >> 1) & 3);
    }
    const uint32_t aSegBase = (uint32_t)(lane >> 4);
    const uint32_t bSegBase = (uint32_t)((lane >> 3) & 1);
    const int ksFlip = wid & 1;

    load_stage(0, 0);
    load_stage(1, 1);

    for (int c = 0; c < 8; c++) {
        if (c < 7) cp_wait<1>(); else cp_wait<0>();
        __syncthreads();
        if (c + 2 < 8) load_stage(c + 2, (c + 2) % 3);
        uint32_t sb = buf + (c % 3) * STAGE_BYTES;
#pragma unroll
        for (int ksi = 0; ksi < 2; ksi++) {
            int ks = ksFlip ? (1 - ksi) : ksi;
            uint32_t ah[2][4], al[2][4], bb[8][2];
            uint32_t aseg = (uint32_t)(ks * 2) + aSegBase;
            uint32_t bseg = (uint32_t)(ks * 2) + bSegBase;
#pragma unroll
            for (int mi = 0; mi < 2; mi++) {
                uint32_t ad = sb + AH_OFF + aRow[mi] + (((aseg ^ aXor[mi])) << 4);
                ldsm4(ah[mi][0], ah[mi][1], ah[mi][2], ah[mi][3], ad);
            }
#pragma unroll
            for (int nt = 0; nt < 4; nt++) {
                uint32_t bd = sb + BH_OFF + bRow[nt] + (((bseg ^ bXor[nt])) << 4);
                ldsm4(bb[nt * 2][0], bb[nt * 2][1], bb[nt * 2 + 1][0], bb[nt * 2 + 1][1], bd);
            }
#pragma unroll
            for (int mi = 0; mi < 2; mi++)
#pragma unroll
                for (int nj = 0; nj < 8; nj++) mma_bf16(acc[mi][nj], ah[mi], bb[nj]);
#pragma unroll
            for (int mi = 0; mi < 2; mi++) {
                uint32_t ad = sb + AL_OFF + aRow[mi] + (((aseg ^ aXor[mi])) << 4);
                ldsm4(al[mi][0], al[mi][1], al[mi][2], al[mi][3], ad);
            }
#pragma unroll
            for (int mi = 0; mi < 2; mi++)
#pragma unroll
                for (int nj = 0; nj < 8; nj++) mma_bf16(acc[mi][nj], al[mi], bb[nj]);
#pragma unroll
            for (int nt = 0; nt < 4; nt++) {
                uint32_t bd = sb + BL_OFF + bRow[nt] + (((bseg ^ bXor[nt])) << 4);
                ldsm4(bb[nt * 2][0], bb[nt * 2][1], bb[nt * 2 + 1][0], bb[nt * 2 + 1][1], bd);
            }
#pragma unroll
            for (int mi = 0; mi < 2; mi++)
#pragma unroll
                for (int nj = 0; nj < 8; nj++) mma_bf16(acc[mi][nj], ah[mi], bb[nj]);
#pragma unroll
            for (int mi = 0; mi < 2; mi++)
#pragma unroll
                for (int nj = 0; nj < 8; nj++) mma_bf16(acc[mi][nj], al[mi], bb[nj]);
        }
    }

    const int grp = lane >> 2, qd = lane & 3;
#pragma unroll
    for (int mi = 0; mi < 2; mi++) {
        int m0r = m0 + wm * 32 + mi * 16 + grp;
        int m1r = m0r + 8;
        int d0v = m0r >> 5, b0v = m0r & 31;
        int d1v = m1r >> 5, b1v = m1r & 31;
        size_t r0 = ((size_t)b0v * DEC_LEN + d0v) * HID;
        size_t r1 = ((size_t)b1v * DEC_LEN + d1v) * HID;
#pragma unroll
        for (int nj = 0; nj < 8; nj++) {
            int cl = n0 + wn * 64 + nj * 8 + qd * 2;
            uint32_t lo;
            uint32_t hi = bf16_split2(acc[mi][nj][0], acc[mi][nj][1], lo);
            *reinterpret_cast<uint32_t*>(&g_pHi[r0 + cl]) = hi;
            *reinterpret_cast<uint32_t*>(&g_pLo[r0 + cl]) = lo;
            hi = bf16_split2(acc[mi][nj][2], acc[mi][nj][3], lo);
            *reinterpret_cast<uint32_t*>(&g_pHi[r1 + cl]) = hi;
            *reinterpret_cast<uint32_t*>(&g_pLo[r1 + cl]) = lo;
        }
    }
}

// =====================================================================
// Kernel 2: score on COMPACTED columns. CTAs beyond n_b exit early.
// Writes raw compact logits (no mask application needed).
// =====================================================================
__global__ __launch_bounds__(256, 2)
void k_score_mma(float* __restrict__ wout) {
    extern __shared__ char dynsmem[];
    const int tid = threadIdx.x;
    const int wid = tid >> 5, lane = tid & 31;
    const int wm = wid & 3;
    const int wn = wid >> 2;
    const int b = blockIdx.z;
    const int d0 = blockIdx.y * 128;
    const int s0 = blockIdx.x * 128;

    const int nvalid = g_nb[b];
    if (s0 >= nvalid) return;                 // whole tile masked away

    uint32_t buf = (smem_u32(dynsmem) + 1023u) & ~1023u;

    const __nv_bfloat16* Ah = g_pHi + ((size_t)b * DEC_LEN + d0) * HID;
    const __nv_bfloat16* Al = g_pLo + ((size_t)b * DEC_LEN + d0) * HID;
    const __nv_bfloat16* Bh = g_eHi + ((size_t)b * ENC_LEN + s0) * HID;
    const __nv_bfloat16* Bl = g_eLo + ((size_t)b * ENC_LEN + s0) * HID;

    auto load_stage = [&](int c, int slot) {
        uint32_t sb = buf + slot * STAGE_BYTES;
        int kofs = c * 32;
#pragma unroll
        for (int i = 0; i < 2; i++) {
            int id = tid + i * 256;
            int row = id >> 2, seg = id & 3;
            uint32_t so = (uint32_t)(row * 64 + ((seg ^ ((row >> 1) & 3)) << 4));
            size_t go = (size_t)row * HID + kofs + seg * 8;
            cp_async16(sb + AH_OFF + so, Ah + go);
            cp_async16(sb + AL_OFF + so, Al + go);
            cp_async16(sb + BH_OFF + so, Bh + go);
            cp_async16(sb + BL_OFF + so, Bl + go);
        }
        cp_commit();
    };

    float acc[2][8][4];
#pragma unroll
    for (int mi = 0; mi < 2; mi++)
#pragma unroll
        for (int nj = 0; nj < 8; nj++)
#pragma unroll
            for (int r = 0; r < 4; r++) acc[mi][nj][r] = 0.f;

    uint32_t aRow[2], aXor[2];
#pragma unroll
    for (int mi = 0; mi < 2; mi++) {
        int r = wm * 32 + mi * 16 + (lane & 15);
        aRow[mi] = (uint32_t)(r * 64);
        aXor[mi] = (uint32_t)((r >> 1) & 3);
    }
    uint32_t bRow[4], bXor[4];
#pragma unroll
    for (int nt = 0; nt < 4; nt++) {
        int r = wn * 64 + nt * 16 + (lane & 7) + ((lane >> 4) << 3);
        bRow[nt] = (uint32_t)(r * 64);
        bXor[nt] = (uint32_t)((r >> 1) & 3);
    }
    const uint32_t aSegBase = (uint32_t)(lane >> 4);
    const uint32_t bSegBase = (uint32_t)((lane >> 3) & 1);
    const int ksFlip = wid & 1;

    load_stage(0, 0);
    load_stage(1, 1);

    for (int c = 0; c < 8; c++) {
        if (c < 7) cp_wait<1>(); else cp_wait<0>();
        __syncthreads();
        if (c + 2 < 8) load_stage(c + 2, (c + 2) % 3);
        uint32_t sb = buf + (c % 3) * STAGE_BYTES;
#pragma unroll
        for (int ksi = 0; ksi < 2; ksi++) {
            int ks = ksFlip ? (1 - ksi) : ksi;
            uint32_t ah[2][4], al[2][4], bb[8][2];
            uint32_t aseg = (uint32_t)(ks * 2) + aSegBase;
            uint32_t bseg = (uint32_t)(ks * 2) + bSegBase;
#pragma unroll
            for (int mi = 0; mi < 2; mi++) {
                uint32_t ad = sb + AH_OFF + aRow[mi] + (((aseg ^ aXor[mi])) << 4);
                ldsm4(ah[mi][0], ah[mi][1], ah[mi][2], ah[mi][3], ad);
            }
#pragma unroll
            for (int nt = 0; nt < 4; nt++) {
                uint32_t bd = sb + BH_OFF + bRow[nt] + (((bseg ^ bXor[nt])) << 4);
                ldsm4(bb[nt * 2][0], bb[nt * 2][1], bb[nt * 2 + 1][0], bb[nt * 2 + 1][1], bd);
            }
#pragma unroll
            for (int mi = 0; mi < 2; mi++)
#pragma unroll
                for (int nj = 0; nj < 8; nj++) mma_bf16(acc[mi][nj], ah[mi], bb[nj]);
#pragma unroll
            for (int mi = 0; mi < 2; mi++) {
                uint32_t ad = sb + AL_OFF + aRow[mi] + (((aseg ^ aXor[mi])) << 4);
                ldsm4(al[mi][0], al[mi][1], al[mi][2], al[mi][3], ad);
            }
#pragma unroll
            for (int mi = 0; mi < 2; mi++)
#pragma unroll
                for (int nj = 0; nj < 8; nj++) mma_bf16(acc[mi][nj], al[mi], bb[nj]);
#pragma unroll
            for (int nt = 0; nt < 4; nt++) {
                uint32_t bd = sb + BL_OFF + bRow[nt] + (((bseg ^ bXor[nt])) << 4);
                ldsm4(bb[nt * 2][0], bb[nt * 2][1], bb[nt * 2 + 1][0], bb[nt * 2 + 1][1], bd);
            }
#pragma unroll
            for (int mi = 0; mi < 2; mi++)
#pragma unroll
                for (int nj = 0; nj < 8; nj++) mma_bf16(acc[mi][nj], ah[mi], bb[nj]);
        }
    }

    // epilogue: compact logits, guarded scalar stores (j < nvalid)
    const int grp = lane >> 2, qd = lane & 3;
#pragma unroll
    for (int mi = 0; mi < 2; mi++) {
        int dr0 = d0 + wm * 32 + mi * 16 + grp;
        int dr1 = dr0 + 8;
        size_t row0 = ((size_t)b * DEC_LEN + dr0) * (size_t)ENC_LEN;
        size_t row1 = ((size_t)b * DEC_LEN + dr1) * (size_t)ENC_LEN;
#pragma unroll
        for (int nj = 0; nj < 8; nj++) {
            int j = s0 + wn * 64 + nj * 8 + qd * 2;
            if (j < nvalid)     { wout[row0 + j] = acc[mi][nj][0]; wout[row1 + j] = acc[mi][nj][2]; }
            if (j + 1 < nvalid) { wout[row0 + j + 1] = acc[mi][nj][1]; wout[row1 + j + 1] = acc[mi][nj][3]; }
        }
    }
}

// =====================================================================
// Kernel 3: softmax over compact logits + scatter full row + sparse attn
// =====================================================================
__global__ __launch_bounds__(256)
void k_softmax_attn(const float* __restrict__ enc, float* __restrict__ wts,
                    float* __restrict__ attn) {
    const int r = blockIdx.x;
    const int b = r >> 9;
    const int d = r & 511;
    const int n = g_nb[b];
    float* row = wts + (size_t)r * ENC_LEN;
    const int tid = threadIdx.x;
    const int lane = tid & 31, warp = tid >> 5;

    __shared__ float wcomp[ENC_LEN];    // compact weights for scatter (8KB)
    __shared__ float redm[8];
    __shared__ float reds[8];
    __shared__ int cnt;
    __shared__ int sidx[256];
    __shared__ float sw[256];
    if (tid == 0) cnt = 0;

    // read compact logits (idx >= n -> -inf sentinel)
    float va[8];
#pragma unroll
    for (int j = 0; j < 8; j++) {
        int idx = tid * 8 + j;
        va[j] = (idx < n) ? row[idx] : -3.4e38f;
    }

    float m = va[0];
#pragma unroll
    for (int j = 1; j < 8; j++) m = fmaxf(m, va[j]);
#pragma unroll
    for (int o = 16; o; o >>= 1) m = fmaxf(m, __shfl_xor_sync(0xffffffffu, m, o));
    if (lane == 0) redm[warp] = m;
    __syncthreads();
    if (tid < 32) {
        float t = (lane < 8) ? redm[lane] : -3.4e38f;
#pragma unroll
        for (int o = 4; o; o >>= 1) t = fmaxf(t, __shfl_xor_sync(0xffffffffu, t, o));
        if (lane == 0) redm[0] = t;
    }
    __syncthreads();
    const float mx = redm[0];

    float e[8];
    float s = 0.f;
#pragma unroll
    for (int j = 0; j < 8; j++) {
        float x = va[j] - mx;
        e[j] = (x > -30.0f) ? __expf(x) : 0.f;
        s += e[j];
    }
#pragma unroll
    for (int o = 16; o; o >>= 1) s += __shfl_xor_sync(0xffffffffu, s, o);
    if (lane == 0) reds[warp] = s;
    __syncthreads();
    if (tid < 32) {
        float t = (lane < 8) ? reds[lane] : 0.f;
#pragma unroll
        for (int o = 4; o; o >>= 1) t += __shfl_xor_sync(0xffffffffu, t, o);
        if (lane == 0) reds[0] = t;
    }
    __syncthreads();
    const float inv = 1.0f / reds[0];

#pragma unroll
    for (int j = 0; j < 8; j++) {
        int idx = tid * 8 + j;
        float w = e[j] * inv;
        wcomp[idx] = w;                        // valid for idx < n; others unused
        if (e[j] > 0.f) {
            int p = atomicAdd(&cnt, 1);
            if (p < 256) { sidx[p] = idx; sw[p] = w; }
        }
    }
    __syncthreads();

    // scatter full row: masked -> exact 0, unmasked -> compact weight
    const int* posb = g_pos + b * ENC_LEN;
#pragma unroll
    for (int i = 0; i < 8; i++) {
        int sidx_full = tid + i * 256;
        int p = posb[sidx_full];
        row[sidx_full] = (p >= 0) ? wcomp[p] : 0.f;
    }

    // sparse attn gather via cidx
    int nc = cnt; if (nc > 256) nc = 256;
    const int* cidxb = g_cidx + b * ENC_LEN;
    float a = 0.f;
    for (int i = 0; i < nc; i++) {
        int s_orig = cidxb[sidx[i]];
        a += sw[i] * enc[((size_t)s_orig * BATCH + b) * HID + tid];
    }
    attn[((size_t)d * BATCH + b) * HID + tid] = a;
}

// =====================================================================
extern "C" void kernel_launch(void* const* d_in, const int* in_sizes, int n_in,
                              void* d_out, int out_size) {
    const float* enc = (const float*)d_in[0];   // (2048, 32, 256)
    const float* dec = (const float*)d_in[1];   // (512, 32, 256)
    const float* W   = (const float*)d_in[2];   // (256, 256)
    const int* mask  = (const int*)d_in[3];     // (2048, 32)

    float* attn = (float*)d_out;
    float* wts  = (float*)d_out + (size_t)DEC_LEN * BATCH * HID;

    static bool attr_done = false;
    if (!attr_done) {
        cudaFuncSetAttribute(k_score_mma, cudaFuncAttributeMaxDynamicSharedMemorySize, SMEM_TOTAL);
        cudaFuncSetAttribute(k_proj_mma, cudaFuncAttributeMaxDynamicSharedMemorySize, SMEM_TOTAL);
        attr_done = true;
    }

    k_mask_scan<<<BATCH, 256>>>(mask);
    k_prep_enc<<<(ENC_LEN * BATCH * HID / 4) / 256, 256>>>(enc);
    k_prep_decw<<<NDEC_BLOCKS + HID, 256>>>(dec, W);
    k_proj_mma<<<dim3(HID / 128, (DEC_LEN * BATCH) / 128), 256, SMEM_TOTAL>>>();
    k_score_mma<<<dim3(ENC_LEN / 128, DEC_LEN / 128, BATCH), 256, SMEM_TOTAL>>>(wts);
    k_softmax_attn<<<BATCH * DEC_LEN, 256>>>(enc, wts, attn);
}

// round 14
// speedup vs baseline: 1.2519x; 1.1026x over previous
#include <cuda_runtime.h>
#include <cuda_bf16.h>
#include <cstdint>
#include <math.h>

#define ENC_LEN 2048
#define DEC_LEN 512
#define BATCH   32
#define HID     256
#define NEGVAL  (-1.0e12f)

// ---------------- static device scratch (allocation-free) ----------------
__device__ __align__(256) __nv_bfloat16 g_pHi[(size_t)BATCH * DEC_LEN * HID];  // proj hi [b][d][k]
__device__ __align__(256) __nv_bfloat16 g_pLo[(size_t)BATCH * DEC_LEN * HID];  // proj lo
__device__ __align__(256) __nv_bfloat16 g_eHi[(size_t)BATCH * ENC_LEN * HID];  // enc hi  [b][j][k] compacted
__device__ __align__(256) __nv_bfloat16 g_eLo[(size_t)BATCH * ENC_LEN * HID];  // enc lo  compacted
__device__ __align__(256) __nv_bfloat16 g_dHi[(size_t)DEC_LEN * BATCH * HID];  // dec hi  [m][k]
__device__ __align__(256) __nv_bfloat16 g_dLo[(size_t)DEC_LEN * BATCH * HID];  // dec lo
__device__ __align__(256) __nv_bfloat16 g_wHi[(size_t)HID * HID];              // W^T hi [n][k]
__device__ __align__(256) __nv_bfloat16 g_wLo[(size_t)HID * HID];              // W^T lo
__device__ int g_cidx[BATCH * ENC_LEN];   // [b][j] -> s
__device__ int g_pos[BATCH * ENC_LEN];    // [b][s] -> j (or -1 if masked)
__device__ int g_nb[BATCH];               // unmasked count per batch

// ---------------- helpers ----------------
__device__ __forceinline__ uint32_t smem_u32(const void* p) {
    uint32_t a;
    asm("{ .reg .u64 t; cvta.to.shared.u64 t, %1; cvt.u32.u64 %0, t; }" : "=r"(a) : "l"(p));
    return a;
}
__device__ __forceinline__ void cp_async16(uint32_t saddr, const void* gaddr) {
    asm volatile("cp.async.cg.shared.global [%0], [%1], 16;" :: "r"(saddr), "l"(gaddr) : "memory");
}
__device__ __forceinline__ void cp_commit() { asm volatile("cp.async.commit_group;" ::: "memory"); }
template <int N>
__device__ __forceinline__ void cp_wait() { asm volatile("cp.async.wait_group %0;" :: "n"(N) : "memory"); }

__device__ __forceinline__ void ldsm4(uint32_t& r0, uint32_t& r1, uint32_t& r2, uint32_t& r3, uint32_t addr) {
    asm volatile("ldmatrix.sync.aligned.m8n8.x4.shared.b16 {%0,%1,%2,%3}, [%4];"
                 : "=r"(r0), "=r"(r1), "=r"(r2), "=r"(r3) : "r"(addr));
}
__device__ __forceinline__ void mma_bf16(float* c, const uint32_t* a, const uint32_t* b) {
    asm volatile(
        "mma.sync.aligned.m16n8k16.row.col.f32.bf16.bf16.f32 "
        "{%0,%1,%2,%3}, {%4,%5,%6,%7}, {%8,%9}, {%0,%1,%2,%3};"
        : "+f"(c[0]), "+f"(c[1]), "+f"(c[2]), "+f"(c[3])
        : "r"(a[0]), "r"(a[1]), "r"(a[2]), "r"(a[3]), "r"(b[0]), "r"(b[1]));
}

__device__ __forceinline__ void bf16_split4(float4 v, uint2& hi, uint2& lo) {
    __nv_bfloat16 hx = __float2bfloat16_rn(v.x), hy = __float2bfloat16_rn(v.y);
    __nv_bfloat16 hz = __float2bfloat16_rn(v.z), hw = __float2bfloat16_rn(v.w);
    __nv_bfloat16 lx = __float2bfloat16_rn(v.x - __bfloat162float(hx));
    __nv_bfloat16 ly = __float2bfloat16_rn(v.y - __bfloat162float(hy));
    __nv_bfloat16 lz = __float2bfloat16_rn(v.z - __bfloat162float(hz));
    __nv_bfloat16 lw = __float2bfloat16_rn(v.w - __bfloat162float(hw));
    __nv_bfloat162 h01 = __halves2bfloat162(hx, hy), h23 = __halves2bfloat162(hz, hw);
    __nv_bfloat162 l01 = __halves2bfloat162(lx, ly), l23 = __halves2bfloat162(lz, lw);
    hi.x = *reinterpret_cast<uint32_t*>(&h01); hi.y = *reinterpret_cast<uint32_t*>(&h23);
    lo.x = *reinterpret_cast<uint32_t*>(&l01); lo.y = *reinterpret_cast<uint32_t*>(&l23);
}
__device__ __forceinline__ uint32_t bf16_split2(float a, float b, uint32_t& lo) {
    __nv_bfloat16 ha = __float2bfloat16_rn(a), hb = __float2bfloat16_rn(b);
    __nv_bfloat16 la = __float2bfloat16_rn(a - __bfloat162float(ha));
    __nv_bfloat16 lb = __float2bfloat16_rn(b - __bfloat162float(hb));
    __nv_bfloat162 h = __halves2bfloat162(ha, hb), l = __halves2bfloat162(la, lb);
    lo = *reinterpret_cast<uint32_t*>(&l);
    return *reinterpret_cast<uint32_t*>(&h);
}

// =====================================================================
// Kernel 0: FUSED dec split + W transpose/split + per-batch mask scan
//   blocks [0, NDEC)            : dec -> g_dHi/g_dLo
//   blocks [NDEC, NDEC+HID)     : W   -> g_wHi/g_wLo (transposed)
//   blocks [NDEC+HID, +BATCH)   : mask prefix scan -> cidx/pos/nb
// =====================================================================
#define NDEC_BLOCKS ((DEC_LEN * BATCH * HID / 4) / 256)
__global__ __launch_bounds__(256)
void k_prep_decw_scan(const float* __restrict__ dec, const float* __restrict__ W,
                      const int* __restrict__ mask) {
    if (blockIdx.x < NDEC_BLOCKS) {
        size_t fid = (size_t)blockIdx.x * 256 + threadIdx.x;
        float4 v = reinterpret_cast<const float4*>(dec)[fid];
        uint2 hi, lo;
        bf16_split4(v, hi, lo);
        reinterpret_cast<uint2*>(g_dHi)[fid] = hi;
        reinterpret_cast<uint2*>(g_dLo)[fid] = lo;
    } else if (blockIdx.x < NDEC_BLOCKS + HID) {
        int n = blockIdx.x - NDEC_BLOCKS;
        int k = threadIdx.x;
        float v = W[(size_t)k * HID + n];
        __nv_bfloat16 h = __float2bfloat16_rn(v);
        __nv_bfloat16 l = __float2bfloat16_rn(v - __bfloat162float(h));
        g_wHi[(size_t)n * HID + k] = h;
        g_wLo[(size_t)n * HID + k] = l;
    } else {
        const int b = blockIdx.x - NDEC_BLOCKS - HID;
        const int t = threadIdx.x;
        __shared__ int sc[256];
        int m[8], cnt = 0;
#pragma unroll
        for (int j = 0; j < 8; j++) {
            int s = t * 8 + j;
            m[j] = mask[(size_t)s * BATCH + b];
            cnt += (m[j] != 0);
        }
        sc[t] = cnt;
        __syncthreads();
        for (int off = 1; off < 256; off <<= 1) {
            int v = (t >= off) ? sc[t - off] : 0;
            __syncthreads();
            sc[t] += v;
            __syncthreads();
        }
        int base = sc[t] - cnt;
#pragma unroll
        for (int j = 0; j < 8; j++) {
            int s = t * 8 + j;
            if (m[j] != 0) {
                g_cidx[b * ENC_LEN + base] = s;
                g_pos[b * ENC_LEN + s] = base;
                base++;
            } else {
                g_pos[b * ENC_LEN + s] = -1;
            }
        }
        if (t == 255) g_nb[b] = sc[255];
    }
}

// =====================================================================
// Kernel 0a: enc (s,b,h) f32 -> bf16 hi/lo, COMPACTED rows [b][j][h]
// =====================================================================
__global__ __launch_bounds__(256)
void k_prep_enc(const float* __restrict__ enc) {
    size_t fid = (size_t)blockIdx.x * 256 + threadIdx.x;
    int h4 = (int)(fid & 63);
    int sb = (int)(fid >> 6);
    int b = sb & 31;
    int s = sb >> 5;
    int p = g_pos[b * ENC_LEN + s];
    if (p < 0) return;
    float4 v = reinterpret_cast<const float4*>(enc)[fid];
    uint2 hi, lo;
    bf16_split4(v, hi, lo);
    size_t o = ((size_t)b * ENC_LEN + p) * 64 + h4;
    reinterpret_cast<uint2*>(g_eHi)[o] = hi;
    reinterpret_cast<uint2*>(g_eLo)[o] = lo;
}

// =====================================================================
// tile machinery
// =====================================================================
#define STAGE_BYTES 32768
#define AH_OFF 0
#define AL_OFF 8192
#define BH_OFF 16384
#define BL_OFF 24576
#define SMEM_TOTAL (3 * STAGE_BYTES + 1024)

// =====================================================================
// Kernel 1: proj = dec @ W^T(T) via bf16 split-4 MMA (unchanged)
// =====================================================================
__global__ __launch_bounds__(256, 2)
void k_proj_mma() {
    extern __shared__ char dynsmem[];
    const int tid = threadIdx.x;
    const int wid = tid >> 5, lane = tid & 31;
    const int wm = wid & 3;
    const int wn = wid >> 2;
    const int n0 = blockIdx.x * 128;
    const int m0 = blockIdx.y * 128;

    uint32_t buf = (smem_u32(dynsmem) + 1023u) & ~1023u;

    const __nv_bfloat16* Ah = g_dHi + (size_t)m0 * HID;
    const __nv_bfloat16* Al = g_dLo + (size_t)m0 * HID;
    const __nv_bfloat16* Bh = g_wHi + (size_t)n0 * HID;
    const __nv_bfloat16* Bl = g_wLo + (size_t)n0 * HID;

    auto load_stage = [&](int c, int slot) {
        uint32_t sb = buf + slot * STAGE_BYTES;
        int kofs = c * 32;
#pragma unroll
        for (int i = 0; i < 2; i++) {
            int id = tid + i * 256;
            int row = id >> 2, seg = id & 3;
            uint32_t so = (uint32_t)(row * 64 + ((seg ^ ((row >> 1) & 3)) << 4));
            size_t go = (size_t)row * HID + kofs + seg * 8;
            cp_async16(sb + AH_OFF + so, Ah + go);
            cp_async16(sb + AL_OFF + so, Al + go);
            cp_async16(sb + BH_OFF + so, Bh + go);
            cp_async16(sb + BL_OFF + so, Bl + go);
        }
        cp_commit();
    };

    float acc[2][8][4];
#pragma unroll
    for (int mi = 0; mi < 2; mi++)
#pragma unroll
        for (int nj = 0; nj < 8; nj++)
#pragma unroll
            for (int r = 0; r < 4; r++) acc[mi][nj][r] = 0.f;

    uint32_t aRow[2], aXor[2];
#pragma unroll
    for (int mi = 0; mi < 2; mi++) {
        int r = wm * 32 + mi * 16 + (lane & 15);
        aRow[mi] = (uint32_t)(r * 64);
        aXor[mi] = (uint32_t)((r >> 1) & 3);
    }
    uint32_t bRow[4], bXor[4];
#pragma unroll
    for (int nt = 0; nt < 4; nt++) {
        int r = wn * 64 + nt * 16 + (lane & 7) + ((lane >> 4) << 3);
        bRow[nt] = (uint32_t)(r * 64);
        bXor[nt] = (uint32_t)((r >> 1) & 3);
    }
    const uint32_t aSegBase = (uint32_t)(lane >> 4);
    const uint32_t bSegBase = (uint32_t)((lane >> 3) & 1);
    const int ksFlip = wid & 1;

    load_stage(0, 0);
    load_stage(1, 1);

    for (int c = 0; c < 8; c++) {
        if (c < 7) cp_wait<1>(); else cp_wait<0>();
        __syncthreads();
        if (c + 2 < 8) load_stage(c + 2, (c + 2) % 3);
        uint32_t sb = buf + (c % 3) * STAGE_BYTES;
#pragma unroll
        for (int ksi = 0; ksi < 2; ksi++) {
            int ks = ksFlip ? (1 - ksi) : ksi;
            uint32_t ah[2][4], al[2][4], bb[8][2];
            uint32_t aseg = (uint32_t)(ks * 2) + aSegBase;
            uint32_t bseg = (uint32_t)(ks * 2) + bSegBase;
#pragma unroll
            for (int mi = 0; mi < 2; mi++) {
                uint32_t ad = sb + AH_OFF + aRow[mi] + (((aseg ^ aXor[mi])) << 4);
                ldsm4(ah[mi][0], ah[mi][1], ah[mi][2], ah[mi][3], ad);
            }
#pragma unroll
            for (int nt = 0; nt < 4; nt++) {
                uint32_t bd = sb + BH_OFF + bRow[nt] + (((bseg ^ bXor[nt])) << 4);
                ldsm4(bb[nt * 2][0], bb[nt * 2][1], bb[nt * 2 + 1][0], bb[nt * 2 + 1][1], bd);
            }
#pragma unroll
            for (int mi = 0; mi < 2; mi++)
#pragma unroll
                for (int nj = 0; nj < 8; nj++) mma_bf16(acc[mi][nj], ah[mi], bb[nj]);
#pragma unroll
            for (int mi = 0; mi < 2; mi++) {
                uint32_t ad = sb + AL_OFF + aRow[mi] + (((aseg ^ aXor[mi])) << 4);
                ldsm4(al[mi][0], al[mi][1], al[mi][2], al[mi][3], ad);
            }
#pragma unroll
            for (int mi = 0; mi < 2; mi++)
#pragma unroll
                for (int nj = 0; nj < 8; nj++) mma_bf16(acc[mi][nj], al[mi], bb[nj]);
#pragma unroll
            for (int nt = 0; nt < 4; nt++) {
                uint32_t bd = sb + BL_OFF + bRow[nt] + (((bseg ^ bXor[nt])) << 4);
                ldsm4(bb[nt * 2][0], bb[nt * 2][1], bb[nt * 2 + 1][0], bb[nt * 2 + 1][1], bd);
            }
#pragma unroll
            for (int mi = 0; mi < 2; mi++)
#pragma unroll
                for (int nj = 0; nj < 8; nj++) mma_bf16(acc[mi][nj], ah[mi], bb[nj]);
#pragma unroll
            for (int mi = 0; mi < 2; mi++)
#pragma unroll
                for (int nj = 0; nj < 8; nj++) mma_bf16(acc[mi][nj], al[mi], bb[nj]);
        }
    }

    const int grp = lane >> 2, qd = lane & 3;
#pragma unroll
    for (int mi = 0; mi < 2; mi++) {
        int m0r = m0 + wm * 32 + mi * 16 + grp;
        int m1r = m0r + 8;
        int d0v = m0r >> 5, b0v = m0r & 31;
        int d1v = m1r >> 5, b1v = m1r & 31;
        size_t r0 = ((size_t)b0v * DEC_LEN + d0v) * HID;
        size_t r1 = ((size_t)b1v * DEC_LEN + d1v) * HID;
#pragma unroll
        for (int nj = 0; nj < 8; nj++) {
            int cl = n0 + wn * 64 + nj * 8 + qd * 2;
            uint32_t lo;
            uint32_t hi = bf16_split2(acc[mi][nj][0], acc[mi][nj][1], lo);
            *reinterpret_cast<uint32_t*>(&g_pHi[r0 + cl]) = hi;
            *reinterpret_cast<uint32_t*>(&g_pLo[r0 + cl]) = lo;
            hi = bf16_split2(acc[mi][nj][2], acc[mi][nj][3], lo);
            *reinterpret_cast<uint32_t*>(&g_pHi[r1 + cl]) = hi;
            *reinterpret_cast<uint32_t*>(&g_pLo[r1 + cl]) = lo;
        }
    }
}

// =====================================================================
// Kernel 2: score on compacted columns; early exit beyond n_b;
// float2 epilogue fast path inside valid region.
// =====================================================================
__global__ __launch_bounds__(256, 2)
void k_score_mma(float* __restrict__ wout) {
    extern __shared__ char dynsmem[];
    const int tid = threadIdx.x;
    const int wid = tid >> 5, lane = tid & 31;
    const int wm = wid & 3;
    const int wn = wid >> 2;
    const int b = blockIdx.z;
    const int d0 = blockIdx.y * 128;
    const int s0 = blockIdx.x * 128;

    const int nvalid = g_nb[b];
    if (s0 >= nvalid) return;

    uint32_t buf = (smem_u32(dynsmem) + 1023u) & ~1023u;

    const __nv_bfloat16* Ah = g_pHi + ((size_t)b * DEC_LEN + d0) * HID;
    const __nv_bfloat16* Al = g_pLo + ((size_t)b * DEC_LEN + d0) * HID;
    const __nv_bfloat16* Bh = g_eHi + ((size_t)b * ENC_LEN + s0) * HID;
    const __nv_bfloat16* Bl = g_eLo + ((size_t)b * ENC_LEN + s0) * HID;

    auto load_stage = [&](int c, int slot) {
        uint32_t sb = buf + slot * STAGE_BYTES;
        int kofs = c * 32;
#pragma unroll
        for (int i = 0; i < 2; i++) {
            int id = tid + i * 256;
            int row = id >> 2, seg = id & 3;
            uint32_t so = (uint32_t)(row * 64 + ((seg ^ ((row >> 1) & 3)) << 4));
            size_t go = (size_t)row * HID + kofs + seg * 8;
            cp_async16(sb + AH_OFF + so, Ah + go);
            cp_async16(sb + AL_OFF + so, Al + go);
            cp_async16(sb + BH_OFF + so, Bh + go);
            cp_async16(sb + BL_OFF + so, Bl + go);
        }
        cp_commit();
    };

    float acc[2][8][4];
#pragma unroll
    for (int mi = 0; mi < 2; mi++)
#pragma unroll
        for (int nj = 0; nj < 8; nj++)
#pragma unroll
            for (int r = 0; r < 4; r++) acc[mi][nj][r] = 0.f;

    uint32_t aRow[2], aXor[2];
#pragma unroll
    for (int mi = 0; mi < 2; mi++) {
        int r = wm * 32 + mi * 16 + (lane & 15);
        aRow[mi] = (uint32_t)(r * 64);
        aXor[mi] = (uint32_t)((r >> 1) & 3);
    }
    uint32_t bRow[4], bXor[4];
#pragma unroll
    for (int nt = 0; nt < 4; nt++) {
        int r = wn * 64 + nt * 16 + (lane & 7) + ((lane >> 4) << 3);
        bRow[nt] = (uint32_t)(r * 64);
        bXor[nt] = (uint32_t)((r >> 1) & 3);
    }
    const uint32_t aSegBase = (uint32_t)(lane >> 4);
    const uint32_t bSegBase = (uint32_t)((lane >> 3) & 1);
    const int ksFlip = wid & 1;

    load_stage(0, 0);
    load_stage(1, 1);

    for (int c = 0; c < 8; c++) {
        if (c < 7) cp_wait<1>(); else cp_wait<0>();
        __syncthreads();
        if (c + 2 < 8) load_stage(c + 2, (c + 2) % 3);
        uint32_t sb = buf + (c % 3) * STAGE_BYTES;
#pragma unroll
        for (int ksi = 0; ksi < 2; ksi++) {
            int ks = ksFlip ? (1 - ksi) : ksi;
            uint32_t ah[2][4], al[2][4], bb[8][2];
            uint32_t aseg = (uint32_t)(ks * 2) + aSegBase;
            uint32_t bseg = (uint32_t)(ks * 2) + bSegBase;
#pragma unroll
            for (int mi = 0; mi < 2; mi++) {
                uint32_t ad = sb + AH_OFF + aRow[mi] + (((aseg ^ aXor[mi])) << 4);
                ldsm4(ah[mi][0], ah[mi][1], ah[mi][2], ah[mi][3], ad);
            }
#pragma unroll
            for (int nt = 0; nt < 4; nt++) {
                uint32_t bd = sb + BH_OFF + bRow[nt] + (((bseg ^ bXor[nt])) << 4);
                ldsm4(bb[nt * 2][0], bb[nt * 2][1], bb[nt * 2 + 1][0], bb[nt * 2 + 1][1], bd);
            }
#pragma unroll
            for (int mi = 0; mi < 2; mi++)
#pragma unroll
                for (int nj = 0; nj < 8; nj++) mma_bf16(acc[mi][nj], ah[mi], bb[nj]);
#pragma unroll
            for (int mi = 0; mi < 2; mi++) {
                uint32_t ad = sb + AL_OFF + aRow[mi] + (((aseg ^ aXor[mi])) << 4);
                ldsm4(al[mi][0], al[mi][1], al[mi][2], al[mi][3], ad);
            }
#pragma unroll
            for (int mi = 0; mi < 2; mi++)
#pragma unroll
                for (int nj = 0; nj < 8; nj++) mma_bf16(acc[mi][nj], al[mi], bb[nj]);
#pragma unroll
            for (int nt = 0; nt < 4; nt++) {
                uint32_t bd = sb + BL_OFF + bRow[nt] + (((bseg ^ bXor[nt])) << 4);
                ldsm4(bb[nt * 2][0], bb[nt * 2][1], bb[nt * 2 + 1][0], bb[nt * 2 + 1][1], bd);
            }
#pragma unroll
            for (int mi = 0; mi < 2; mi++)
#pragma unroll
                for (int nj = 0; nj < 8; nj++) mma_bf16(acc[mi][nj], ah[mi], bb[nj]);
        }
    }

    const int grp = lane >> 2, qd = lane & 3;
#pragma unroll
    for (int mi = 0; mi < 2; mi++) {
        int dr0 = d0 + wm * 32 + mi * 16 + grp;
        int dr1 = dr0 + 8;
        size_t row0 = ((size_t)b * DEC_LEN + dr0) * (size_t)ENC_LEN;
        size_t row1 = ((size_t)b * DEC_LEN + dr1) * (size_t)ENC_LEN;
#pragma unroll
        for (int nj = 0; nj < 8; nj++) {
            int j = s0 + wn * 64 + nj * 8 + qd * 2;
            if (j + 1 < nvalid) {
                *reinterpret_cast<float2*>(&wout[row0 + j]) = make_float2(acc[mi][nj][0], acc[mi][nj][1]);
                *reinterpret_cast<float2*>(&wout[row1 + j]) = make_float2(acc[mi][nj][2], acc[mi][nj][3]);
            } else if (j < nvalid) {
                wout[row0 + j] = acc[mi][nj][0];
                wout[row1 + j] = acc[mi][nj][2];
            }
        }
    }
}

// =====================================================================
// Kernel 3: softmax over compact logits; scatter via cidx into smem
// full-row; float4 weight stores; sparse attn with original indices.
// =====================================================================
__global__ __launch_bounds__(256)
void k_softmax_attn(const float* __restrict__ enc, float* __restrict__ wts,
                    float* __restrict__ attn) {
    const int r = blockIdx.x;
    const int b = r >> 9;
    const int d = r & 511;
    const int n = g_nb[b];
    float* row = wts + (size_t)r * ENC_LEN;
    const int tid = threadIdx.x;
    const int lane = tid & 31, warp = tid >> 5;

    __shared__ __align__(16) float full[ENC_LEN];   // 8KB
    __shared__ float redm[8];
    __shared__ float reds[8];
    __shared__ int cnt;
    __shared__ int sidx[256];
    __shared__ float sw[256];
    if (tid == 0) cnt = 0;
#pragma unroll
    for (int i = 0; i < 8; i++) full[tid + i * 256] = 0.f;
    // (zero-init ordered before scatter by the reduction __syncthreads below)

    float va[8];
#pragma unroll
    for (int j = 0; j < 8; j++) {
        int idx = tid * 8 + j;
        va[j] = (idx < n) ? row[idx] : -3.4e38f;
    }

    float m = va[0];
#pragma unroll
    for (int j = 1; j < 8; j++) m = fmaxf(m, va[j]);
#pragma unroll
    for (int o = 16; o; o >>= 1) m = fmaxf(m, __shfl_xor_sync(0xffffffffu, m, o));
    if (lane == 0) redm[warp] = m;
    __syncthreads();
    if (tid < 32) {
        float t = (lane < 8) ? redm[lane] : -3.4e38f;
#pragma unroll
        for (int o = 4; o; o >>= 1) t = fmaxf(t, __shfl_xor_sync(0xffffffffu, t, o));
        if (lane == 0) redm[0] = t;
    }
    __syncthreads();
    const float mx = redm[0];

    float e[8];
    float s = 0.f;
#pragma unroll
    for (int j = 0; j < 8; j++) {
        float x = va[j] - mx;
        e[j] = (x > -30.0f) ? __expf(x) : 0.f;
        s += e[j];
    }
#pragma unroll
    for (int o = 16; o; o >>= 1) s += __shfl_xor_sync(0xffffffffu, s, o);
    if (lane == 0) reds[warp] = s;
    __syncthreads();
    if (tid < 32) {
        float t = (lane < 8) ? reds[lane] : 0.f;
#pragma unroll
        for (int o = 4; o; o >>= 1) t += __shfl_xor_sync(0xffffffffu, t, o);
        if (lane == 0) reds[0] = t;
    }
    __syncthreads();
    const float inv = 1.0f / reds[0];

    // scatter compact weights to original positions in smem full-row
    const int* cidxb = g_cidx + b * ENC_LEN;
#pragma unroll
    for (int j = 0; j < 8; j++) {
        int idx = tid * 8 + j;
        if (idx < n) {
            float w = e[j] * inv;
            int sorig = cidxb[idx];
            full[sorig] = w;
            if (e[j] > 0.f) {
                int p = atomicAdd(&cnt, 1);
                if (p < 256) { sidx[p] = sorig; sw[p] = w; }
            }
        }
    }
    __syncthreads();

    // vectorized full-row store (masked positions remain exact 0)
#pragma unroll
    for (int i = 0; i < 2; i++) {
        reinterpret_cast<float4*>(row)[tid + i * 256] =
            reinterpret_cast<const float4*>(full)[tid + i * 256];
    }

    // sparse attn gather (original indices already collected)
    int nc = cnt; if (nc > 256) nc = 256;
    float a = 0.f;
    for (int i = 0; i < nc; i++) {
        a += sw[i] * enc[((size_t)sidx[i] * BATCH + b) * HID + tid];
    }
    attn[((size_t)d * BATCH + b) * HID + tid] = a;
}

// =====================================================================
extern "C" void kernel_launch(void* const* d_in, const int* in_sizes, int n_in,
                              void* d_out, int out_size) {
    const float* enc = (const float*)d_in[0];   // (2048, 32, 256)
    const float* dec = (const float*)d_in[1];   // (512, 32, 256)
    const float* W   = (const float*)d_in[2];   // (256, 256)
    const int* mask  = (const int*)d_in[3];     // (2048, 32)

    float* attn = (float*)d_out;
    float* wts  = (float*)d_out + (size_t)DEC_LEN * BATCH * HID;

    static bool attr_done = false;
    if (!attr_done) {
        cudaFuncSetAttribute(k_score_mma, cudaFuncAttributeMaxDynamicSharedMemorySize, SMEM_TOTAL);
        cudaFuncSetAttribute(k_proj_mma, cudaFuncAttributeMaxDynamicSharedMemorySize, SMEM_TOTAL);
        attr_done = true;
    }

    k_prep_decw_scan<<<NDEC_BLOCKS + HID + BATCH, 256>>>(dec, W, mask);
    k_prep_enc<<<(ENC_LEN * BATCH * HID / 4) / 256, 256>>>(enc);
    k_proj_mma<<<dim3(HID / 128, (DEC_LEN * BATCH) / 128), 256, SMEM_TOTAL>>>();
    k_score_mma<<<dim3(ENC_LEN / 128, DEC_LEN / 128, BATCH), 256, SMEM_TOTAL>>>(wts);
    k_softmax_attn<<<BATCH * DEC_LEN, 256>>>(enc, wts, attn);
}

// round 15
// speedup vs baseline: 1.3005x; 1.0388x over previous
#include <cuda_runtime.h>
#include <cuda_bf16.h>
#include <cstdint>
#include <math.h>

#define ENC_LEN 2048
#define DEC_LEN 512
#define BATCH   32
#define HID     256
#define NEGVAL  (-1.0e12f)

// ---------------- static device scratch (allocation-free) ----------------
__device__ __align__(256) __nv_bfloat16 g_pHi[(size_t)BATCH * DEC_LEN * HID];  // proj hi [b][d][k]
__device__ __align__(256) __nv_bfloat16 g_pLo[(size_t)BATCH * DEC_LEN * HID];  // proj lo
__device__ __align__(256) __nv_bfloat16 g_eHi[(size_t)BATCH * ENC_LEN * HID];  // enc hi  [b][j][k] compacted
__device__ __align__(256) __nv_bfloat16 g_eLo[(size_t)BATCH * ENC_LEN * HID];  // enc lo  compacted
__device__ __align__(256) __nv_bfloat16 g_dHi[(size_t)DEC_LEN * BATCH * HID];  // dec hi  [m][k]
__device__ __align__(256) __nv_bfloat16 g_dLo[(size_t)DEC_LEN * BATCH * HID];  // dec lo
__device__ __align__(256) __nv_bfloat16 g_wHi[(size_t)HID * HID];              // W^T hi [n][k]
__device__ __align__(256) __nv_bfloat16 g_wLo[(size_t)HID * HID];              // W^T lo
__device__ int g_cidx[BATCH * ENC_LEN];   // [b][j] -> s
__device__ int g_pos[BATCH * ENC_LEN];    // [b][s] -> j (or -1 if masked)
__device__ int g_nb[BATCH];               // unmasked count per batch

// ---------------- helpers ----------------
__device__ __forceinline__ uint32_t smem_u32(const void* p) {
    uint32_t a;
    asm("{ .reg .u64 t; cvta.to.shared.u64 t, %1; cvt.u32.u64 %0, t; }" : "=r"(a) : "l"(p));
    return a;
}
__device__ __forceinline__ void cp_async16(uint32_t saddr, const void* gaddr) {
    asm volatile("cp.async.cg.shared.global [%0], [%1], 16;" :: "r"(saddr), "l"(gaddr) : "memory");
}
__device__ __forceinline__ void cp_commit() { asm volatile("cp.async.commit_group;" ::: "memory"); }
template <int N>
__device__ __forceinline__ void cp_wait() { asm volatile("cp.async.wait_group %0;" :: "n"(N) : "memory"); }

__device__ __forceinline__ void ldsm4(uint32_t& r0, uint32_t& r1, uint32_t& r2, uint32_t& r3, uint32_t addr) {
    asm volatile("ldmatrix.sync.aligned.m8n8.x4.shared.b16 {%0,%1,%2,%3}, [%4];"
                 : "=r"(r0), "=r"(r1), "=r"(r2), "=r"(r3) : "r"(addr));
}
__device__ __forceinline__ void mma_bf16(float* c, const uint32_t* a, const uint32_t* b) {
    asm volatile(
        "mma.sync.aligned.m16n8k16.row.col.f32.bf16.bf16.f32 "
        "{%0,%1,%2,%3}, {%4,%5,%6,%7}, {%8,%9}, {%0,%1,%2,%3};"
        : "+f"(c[0]), "+f"(c[1]), "+f"(c[2]), "+f"(c[3])
        : "r"(a[0]), "r"(a[1]), "r"(a[2]), "r"(a[3]), "r"(b[0]), "r"(b[1]));
}

__device__ __forceinline__ void bf16_split4(float4 v, uint2& hi, uint2& lo) {
    __nv_bfloat16 hx = __float2bfloat16_rn(v.x), hy = __float2bfloat16_rn(v.y);
    __nv_bfloat16 hz = __float2bfloat16_rn(v.z), hw = __float2bfloat16_rn(v.w);
    __nv_bfloat16 lx = __float2bfloat16_rn(v.x - __bfloat162float(hx));
    __nv_bfloat16 ly = __float2bfloat16_rn(v.y - __bfloat162float(hy));
    __nv_bfloat16 lz = __float2bfloat16_rn(v.z - __bfloat162float(hz));
    __nv_bfloat16 lw = __float2bfloat16_rn(v.w - __bfloat162float(hw));
    __nv_bfloat162 h01 = __halves2bfloat162(hx, hy), h23 = __halves2bfloat162(hz, hw);
    __nv_bfloat162 l01 = __halves2bfloat162(lx, ly), l23 = __halves2bfloat162(lz, lw);
    hi.x = *reinterpret_cast<uint32_t*>(&h01); hi.y = *reinterpret_cast<uint32_t*>(&h23);
    lo.x = *reinterpret_cast<uint32_t*>(&l01); lo.y = *reinterpret_cast<uint32_t*>(&l23);
}
__device__ __forceinline__ uint32_t bf16_split2(float a, float b, uint32_t& lo) {
    __nv_bfloat16 ha = __float2bfloat16_rn(a), hb = __float2bfloat16_rn(b);
    __nv_bfloat16 la = __float2bfloat16_rn(a - __bfloat162float(ha));
    __nv_bfloat16 lb = __float2bfloat16_rn(b - __bfloat162float(hb));
    __nv_bfloat162 h = __halves2bfloat162(ha, hb), l = __halves2bfloat162(la, lb);
    lo = *reinterpret_cast<uint32_t*>(&l);
    return *reinterpret_cast<uint32_t*>(&h);
}

// =====================================================================
// Kernel 0: FUSED dec split + W transpose/split + per-batch mask scan
// =====================================================================
#define NDEC_BLOCKS ((DEC_LEN * BATCH * HID / 4) / 256)
__global__ __launch_bounds__(256)
void k_prep_decw_scan(const float* __restrict__ dec, const float* __restrict__ W,
                      const int* __restrict__ mask) {
    if (blockIdx.x < NDEC_BLOCKS) {
        size_t fid = (size_t)blockIdx.x * 256 + threadIdx.x;
        float4 v = reinterpret_cast<const float4*>(dec)[fid];
        uint2 hi, lo;
        bf16_split4(v, hi, lo);
        reinterpret_cast<uint2*>(g_dHi)[fid] = hi;
        reinterpret_cast<uint2*>(g_dLo)[fid] = lo;
    } else if (blockIdx.x < NDEC_BLOCKS + HID) {
        int n = blockIdx.x - NDEC_BLOCKS;
        int k = threadIdx.x;
        float v = W[(size_t)k * HID + n];
        __nv_bfloat16 h = __float2bfloat16_rn(v);
        __nv_bfloat16 l = __float2bfloat16_rn(v - __bfloat162float(h));
        g_wHi[(size_t)n * HID + k] = h;
        g_wLo[(size_t)n * HID + k] = l;
    } else {
        const int b = blockIdx.x - NDEC_BLOCKS - HID;
        const int t = threadIdx.x;
        __shared__ int sc[256];
        int m[8], cnt = 0;
#pragma unroll
        for (int j = 0; j < 8; j++) {
            int s = t * 8 + j;
            m[j] = mask[(size_t)s * BATCH + b];
            cnt += (m[j] != 0);
        }
        sc[t] = cnt;
        __syncthreads();
        for (int off = 1; off < 256; off <<= 1) {
            int v = (t >= off) ? sc[t - off] : 0;
            __syncthreads();
            sc[t] += v;
            __syncthreads();
        }
        int base = sc[t] - cnt;
#pragma unroll
        for (int j = 0; j < 8; j++) {
            int s = t * 8 + j;
            if (m[j] != 0) {
                g_cidx[b * ENC_LEN + base] = s;
                g_pos[b * ENC_LEN + s] = base;
                base++;
            } else {
                g_pos[b * ENC_LEN + s] = -1;
            }
        }
        if (t == 255) g_nb[b] = sc[255];
    }
}

// =====================================================================
// Kernel 0a: enc (s,b,h) f32 -> bf16 hi/lo, COMPACTED rows [b][j][h]
// =====================================================================
__global__ __launch_bounds__(256)
void k_prep_enc(const float* __restrict__ enc) {
    size_t fid = (size_t)blockIdx.x * 256 + threadIdx.x;
    int h4 = (int)(fid & 63);
    int sb = (int)(fid >> 6);
    int b = sb & 31;
    int s = sb >> 5;
    int p = g_pos[b * ENC_LEN + s];
    if (p < 0) return;
    float4 v = reinterpret_cast<const float4*>(enc)[fid];
    uint2 hi, lo;
    bf16_split4(v, hi, lo);
    size_t o = ((size_t)b * ENC_LEN + p) * 64 + h4;
    reinterpret_cast<uint2*>(g_eHi)[o] = hi;
    reinterpret_cast<uint2*>(g_eLo)[o] = lo;
}

// =====================================================================
// tile machinery
// =====================================================================
#define STAGE_BYTES 32768
#define AH_OFF 0
#define AL_OFF 8192
#define BH_OFF 16384
#define BL_OFF 24576
#define SMEM_TOTAL (3 * STAGE_BYTES + 1024)

// =====================================================================
// Kernel 1: proj = dec @ W^T(T) via bf16 split-4 MMA (unchanged)
// =====================================================================
__global__ __launch_bounds__(256, 2)
void k_proj_mma() {
    extern __shared__ char dynsmem[];
    const int tid = threadIdx.x;
    const int wid = tid >> 5, lane = tid & 31;
    const int wm = wid & 3;
    const int wn = wid >> 2;
    const int n0 = blockIdx.x * 128;
    const int m0 = blockIdx.y * 128;

    uint32_t buf = (smem_u32(dynsmem) + 1023u) & ~1023u;

    const __nv_bfloat16* Ah = g_dHi + (size_t)m0 * HID;
    const __nv_bfloat16* Al = g_dLo + (size_t)m0 * HID;
    const __nv_bfloat16* Bh = g_wHi + (size_t)n0 * HID;
    const __nv_bfloat16* Bl = g_wLo + (size_t)n0 * HID;

    auto load_stage = [&](int c, int slot) {
        uint32_t sb = buf + slot * STAGE_BYTES;
        int kofs = c * 32;
#pragma unroll
        for (int i = 0; i < 2; i++) {
            int id = tid + i * 256;
            int row = id >> 2, seg = id & 3;
            uint32_t so = (uint32_t)(row * 64 + ((seg ^ ((row >> 1) & 3)) << 4));
            size_t go = (size_t)row * HID + kofs + seg * 8;
            cp_async16(sb + AH_OFF + so, Ah + go);
            cp_async16(sb + AL_OFF + so, Al + go);
            cp_async16(sb + BH_OFF + so, Bh + go);
            cp_async16(sb + BL_OFF + so, Bl + go);
        }
        cp_commit();
    };

    float acc[2][8][4];
#pragma unroll
    for (int mi = 0; mi < 2; mi++)
#pragma unroll
        for (int nj = 0; nj < 8; nj++)
#pragma unroll
            for (int r = 0; r < 4; r++) acc[mi][nj][r] = 0.f;

    uint32_t aRow[2], aXor[2];
#pragma unroll
    for (int mi = 0; mi < 2; mi++) {
        int r = wm * 32 + mi * 16 + (lane & 15);
        aRow[mi] = (uint32_t)(r * 64);
        aXor[mi] = (uint32_t)((r >> 1) & 3);
    }
    uint32_t bRow[4], bXor[4];
#pragma unroll
    for (int nt = 0; nt < 4; nt++) {
        int r = wn * 64 + nt * 16 + (lane & 7) + ((lane >> 4) << 3);
        bRow[nt] = (uint32_t)(r * 64);
        bXor[nt] = (uint32_t)((r >> 1) & 3);
    }
    const uint32_t aSegBase = (uint32_t)(lane >> 4);
    const uint32_t bSegBase = (uint32_t)((lane >> 3) & 1);
    const int ksFlip = wid & 1;

    load_stage(0, 0);
    load_stage(1, 1);

    for (int c = 0; c < 8; c++) {
        if (c < 7) cp_wait<1>(); else cp_wait<0>();
        __syncthreads();
        if (c + 2 < 8) load_stage(c + 2, (c + 2) % 3);
        uint32_t sb = buf + (c % 3) * STAGE_BYTES;
#pragma unroll
        for (int ksi = 0; ksi < 2; ksi++) {
            int ks = ksFlip ? (1 - ksi) : ksi;
            uint32_t ah[2][4], al[2][4], bb[8][2];
            uint32_t aseg = (uint32_t)(ks * 2) + aSegBase;
            uint32_t bseg = (uint32_t)(ks * 2) + bSegBase;
#pragma unroll
            for (int mi = 0; mi < 2; mi++) {
                uint32_t ad = sb + AH_OFF + aRow[mi] + (((aseg ^ aXor[mi])) << 4);
                ldsm4(ah[mi][0], ah[mi][1], ah[mi][2], ah[mi][3], ad);
            }
#pragma unroll
            for (int nt = 0; nt < 4; nt++) {
                uint32_t bd = sb + BH_OFF + bRow[nt] + (((bseg ^ bXor[nt])) << 4);
                ldsm4(bb[nt * 2][0], bb[nt * 2][1], bb[nt * 2 + 1][0], bb[nt * 2 + 1][1], bd);
            }
#pragma unroll
            for (int mi = 0; mi < 2; mi++)
#pragma unroll
                for (int nj = 0; nj < 8; nj++) mma_bf16(acc[mi][nj], ah[mi], bb[nj]);
#pragma unroll
            for (int mi = 0; mi < 2; mi++) {
                uint32_t ad = sb + AL_OFF + aRow[mi] + (((aseg ^ aXor[mi])) << 4);
                ldsm4(al[mi][0], al[mi][1], al[mi][2], al[mi][3], ad);
            }
#pragma unroll
            for (int mi = 0; mi < 2; mi++)
#pragma unroll
                for (int nj = 0; nj < 8; nj++) mma_bf16(acc[mi][nj], al[mi], bb[nj]);
#pragma unroll
            for (int nt = 0; nt < 4; nt++) {
                uint32_t bd = sb + BL_OFF + bRow[nt] + (((bseg ^ bXor[nt])) << 4);
                ldsm4(bb[nt * 2][0], bb[nt * 2][1], bb[nt * 2 + 1][0], bb[nt * 2 + 1][1], bd);
            }
#pragma unroll
            for (int mi = 0; mi < 2; mi++)
#pragma unroll
                for (int nj = 0; nj < 8; nj++) mma_bf16(acc[mi][nj], ah[mi], bb[nj]);
#pragma unroll
            for (int mi = 0; mi < 2; mi++)
#pragma unroll
                for (int nj = 0; nj < 8; nj++) mma_bf16(acc[mi][nj], al[mi], bb[nj]);
        }
    }

    const int grp = lane >> 2, qd = lane & 3;
#pragma unroll
    for (int mi = 0; mi < 2; mi++) {
        int m0r = m0 + wm * 32 + mi * 16 + grp;
        int m1r = m0r + 8;
        int d0v = m0r >> 5, b0v = m0r & 31;
        int d1v = m1r >> 5, b1v = m1r & 31;
        size_t r0 = ((size_t)b0v * DEC_LEN + d0v) * HID;
        size_t r1 = ((size_t)b1v * DEC_LEN + d1v) * HID;
#pragma unroll
        for (int nj = 0; nj < 8; nj++) {
            int cl = n0 + wn * 64 + nj * 8 + qd * 2;
            uint32_t lo;
            uint32_t hi = bf16_split2(acc[mi][nj][0], acc[mi][nj][1], lo);
            *reinterpret_cast<uint32_t*>(&g_pHi[r0 + cl]) = hi;
            *reinterpret_cast<uint32_t*>(&g_pLo[r0 + cl]) = lo;
            hi = bf16_split2(acc[mi][nj][2], acc[mi][nj][3], lo);
            *reinterpret_cast<uint32_t*>(&g_pHi[r1 + cl]) = hi;
            *reinterpret_cast<uint32_t*>(&g_pLo[r1 + cl]) = lo;
        }
    }
}

// =====================================================================
// Kernel 2: score on compacted columns (unchanged from round 14)
// =====================================================================
__global__ __launch_bounds__(256, 2)
void k_score_mma(float* __restrict__ wout) {
    extern __shared__ char dynsmem[];
    const int tid = threadIdx.x;
    const int wid = tid >> 5, lane = tid & 31;
    const int wm = wid & 3;
    const int wn = wid >> 2;
    const int b = blockIdx.z;
    const int d0 = blockIdx.y * 128;
    const int s0 = blockIdx.x * 128;

    const int nvalid = g_nb[b];
    if (s0 >= nvalid) return;

    uint32_t buf = (smem_u32(dynsmem) + 1023u) & ~1023u;

    const __nv_bfloat16* Ah = g_pHi + ((size_t)b * DEC_LEN + d0) * HID;
    const __nv_bfloat16* Al = g_pLo + ((size_t)b * DEC_LEN + d0) * HID;
    const __nv_bfloat16* Bh = g_eHi + ((size_t)b * ENC_LEN + s0) * HID;
    const __nv_bfloat16* Bl = g_eLo + ((size_t)b * ENC_LEN + s0) * HID;

    auto load_stage = [&](int c, int slot) {
        uint32_t sb = buf + slot * STAGE_BYTES;
        int kofs = c * 32;
#pragma unroll
        for (int i = 0; i < 2; i++) {
            int id = tid + i * 256;
            int row = id >> 2, seg = id & 3;
            uint32_t so = (uint32_t)(row * 64 + ((seg ^ ((row >> 1) & 3)) << 4));
            size_t go = (size_t)row * HID + kofs + seg * 8;
            cp_async16(sb + AH_OFF + so, Ah + go);
            cp_async16(sb + AL_OFF + so, Al + go);
            cp_async16(sb + BH_OFF + so, Bh + go);
            cp_async16(sb + BL_OFF + so, Bl + go);
        }
        cp_commit();
    };

    float acc[2][8][4];
#pragma unroll
    for (int mi = 0; mi < 2; mi++)
#pragma unroll
        for (int nj = 0; nj < 8; nj++)
#pragma unroll
            for (int r = 0; r < 4; r++) acc[mi][nj][r] = 0.f;

    uint32_t aRow[2], aXor[2];
#pragma unroll
    for (int mi = 0; mi < 2; mi++) {
        int r = wm * 32 + mi * 16 + (lane & 15);
        aRow[mi] = (uint32_t)(r * 64);
        aXor[mi] = (uint32_t)((r >> 1) & 3);
    }
    uint32_t bRow[4], bXor[4];
#pragma unroll
    for (int nt = 0; nt < 4; nt++) {
        int r = wn * 64 + nt * 16 + (lane & 7) + ((lane >> 4) << 3);
        bRow[nt] = (uint32_t)(r * 64);
        bXor[nt] = (uint32_t)((r >> 1) & 3);
    }
    const uint32_t aSegBase = (uint32_t)(lane >> 4);
    const uint32_t bSegBase = (uint32_t)((lane >> 3) & 1);
    const int ksFlip = wid & 1;

    load_stage(0, 0);
    load_stage(1, 1);

    for (int c = 0; c < 8; c++) {
        if (c < 7) cp_wait<1>(); else cp_wait<0>();
        __syncthreads();
        if (c + 2 < 8) load_stage(c + 2, (c + 2) % 3);
        uint32_t sb = buf + (c % 3) * STAGE_BYTES;
#pragma unroll
        for (int ksi = 0; ksi < 2; ksi++) {
            int ks = ksFlip ? (1 - ksi) : ksi;
            uint32_t ah[2][4], al[2][4], bb[8][2];
            uint32_t aseg = (uint32_t)(ks * 2) + aSegBase;
            uint32_t bseg = (uint32_t)(ks * 2) + bSegBase;
#pragma unroll
            for (int mi = 0; mi < 2; mi++) {
                uint32_t ad = sb + AH_OFF + aRow[mi] + (((aseg ^ aXor[mi])) << 4);
                ldsm4(ah[mi][0], ah[mi][1], ah[mi][2], ah[mi][3], ad);
            }
#pragma unroll
            for (int nt = 0; nt < 4; nt++) {
                uint32_t bd = sb + BH_OFF + bRow[nt] + (((bseg ^ bXor[nt])) << 4);
                ldsm4(bb[nt * 2][0], bb[nt * 2][1], bb[nt * 2 + 1][0], bb[nt * 2 + 1][1], bd);
            }
#pragma unroll
            for (int mi = 0; mi < 2; mi++)
#pragma unroll
                for (int nj = 0; nj < 8; nj++) mma_bf16(acc[mi][nj], ah[mi], bb[nj]);
#pragma unroll
            for (int mi = 0; mi < 2; mi++) {
                uint32_t ad = sb + AL_OFF + aRow[mi] + (((aseg ^ aXor[mi])) << 4);
                ldsm4(al[mi][0], al[mi][1], al[mi][2], al[mi][3], ad);
            }
#pragma unroll
            for (int mi = 0; mi < 2; mi++)
#pragma unroll
                for (int nj = 0; nj < 8; nj++) mma_bf16(acc[mi][nj], al[mi], bb[nj]);
#pragma unroll
            for (int nt = 0; nt < 4; nt++) {
                uint32_t bd = sb + BL_OFF + bRow[nt] + (((bseg ^ bXor[nt])) << 4);
                ldsm4(bb[nt * 2][0], bb[nt * 2][1], bb[nt * 2 + 1][0], bb[nt * 2 + 1][1], bd);
            }
#pragma unroll
            for (int mi = 0; mi < 2; mi++)
#pragma unroll
                for (int nj = 0; nj < 8; nj++) mma_bf16(acc[mi][nj], ah[mi], bb[nj]);
        }
    }

    const int grp = lane >> 2, qd = lane & 3;
#pragma unroll
    for (int mi = 0; mi < 2; mi++) {
        int dr0 = d0 + wm * 32 + mi * 16 + grp;
        int dr1 = dr0 + 8;
        size_t row0 = ((size_t)b * DEC_LEN + dr0) * (size_t)ENC_LEN;
        size_t row1 = ((size_t)b * DEC_LEN + dr1) * (size_t)ENC_LEN;
#pragma unroll
        for (int nj = 0; nj < 8; nj++) {
            int j = s0 + wn * 64 + nj * 8 + qd * 2;
            if (j + 1 < nvalid) {
                *reinterpret_cast<float2*>(&wout[row0 + j]) = make_float2(acc[mi][nj][0], acc[mi][nj][1]);
                *reinterpret_cast<float2*>(&wout[row1 + j]) = make_float2(acc[mi][nj][2], acc[mi][nj][3]);
            } else if (j < nvalid) {
                wout[row0 + j] = acc[mi][nj][0];
                wout[row1 + j] = acc[mi][nj][2];
            }
        }
    }
}

// =====================================================================
// Kernel 3: DUAL-ROW softmax: block handles rows 2r, 2r+1 (same batch).
// One shared reduction ladder for both rows; scatter both via cidx into
// smem full-rows; float4 stores; sparse attn for both rows.
// =====================================================================
__global__ __launch_bounds__(256)
void k_softmax_attn(const float* __restrict__ enc, float* __restrict__ wts,
                    float* __restrict__ attn) {
    const int pr = blockIdx.x;            // 0..8191
    const int r0 = pr * 2, r1 = r0 + 1;
    const int b = r0 >> 9;
    const int d0 = r0 & 511, d1 = d0 + 1;
    const int n = g_nb[b];
    float* row0 = wts + (size_t)r0 * ENC_LEN;
    float* row1 = wts + (size_t)r1 * ENC_LEN;
    const int tid = threadIdx.x;
    const int lane = tid & 31, warp = tid >> 5;

    __shared__ __align__(16) float full0[ENC_LEN];
    __shared__ __align__(16) float full1[ENC_LEN];
    __shared__ float redm[2][8];
    __shared__ float reds[2][8];
    __shared__ int cnt0, cnt1;
    __shared__ int sidx0[128], sidx1[128];
    __shared__ float sw0[128], sw1[128];
    if (tid == 0) { cnt0 = 0; cnt1 = 0; }
#pragma unroll
    for (int i = 0; i < 8; i++) { full0[tid + i * 256] = 0.f; full1[tid + i * 256] = 0.f; }

    float va0[8], va1[8];
#pragma unroll
    for (int j = 0; j < 8; j++) {
        int idx = tid * 8 + j;
        bool v = idx < n;
        va0[j] = v ? row0[idx] : -3.4e38f;
        va1[j] = v ? row1[idx] : -3.4e38f;
    }

    // joint max reduction
    float m0 = va0[0], m1 = va1[0];
#pragma unroll
    for (int j = 1; j < 8; j++) { m0 = fmaxf(m0, va0[j]); m1 = fmaxf(m1, va1[j]); }
#pragma unroll
    for (int o = 16; o; o >>= 1) {
        m0 = fmaxf(m0, __shfl_xor_sync(0xffffffffu, m0, o));
        m1 = fmaxf(m1, __shfl_xor_sync(0xffffffffu, m1, o));
    }
    if (lane == 0) { redm[0][warp] = m0; redm[1][warp] = m1; }
    __syncthreads();
    if (tid < 32) {
        float t0 = (lane < 8) ? redm[0][lane] : -3.4e38f;
        float t1 = (lane < 8) ? redm[1][lane] : -3.4e38f;
#pragma unroll
        for (int o = 4; o; o >>= 1) {
            t0 = fmaxf(t0, __shfl_xor_sync(0xffffffffu, t0, o));
            t1 = fmaxf(t1, __shfl_xor_sync(0xffffffffu, t1, o));
        }
        if (lane == 0) { redm[0][0] = t0; redm[1][0] = t1; }
    }
    __syncthreads();
    const float mx0 = redm[0][0], mx1 = redm[1][0];

    // joint exp + sum
    float e0[8], e1[8];
    float s0 = 0.f, s1 = 0.f;
#pragma unroll
    for (int j = 0; j < 8; j++) {
        float x0 = va0[j] - mx0, x1 = va1[j] - mx1;
        e0[j] = (x0 > -30.0f) ? __expf(x0) : 0.f;
        e1[j] = (x1 > -30.0f) ? __expf(x1) : 0.f;
        s0 += e0[j]; s1 += e1[j];
    }
#pragma unroll
    for (int o = 16; o; o >>= 1) {
        s0 += __shfl_xor_sync(0xffffffffu, s0, o);
        s1 += __shfl_xor_sync(0xffffffffu, s1, o);
    }
    if (lane == 0) { reds[0][warp] = s0; reds[1][warp] = s1; }
    __syncthreads();
    if (tid < 32) {
        float t0 = (lane < 8) ? reds[0][lane] : 0.f;
        float t1 = (lane < 8) ? reds[1][lane] : 0.f;
#pragma unroll
        for (int o = 4; o; o >>= 1) {
            t0 += __shfl_xor_sync(0xffffffffu, t0, o);
            t1 += __shfl_xor_sync(0xffffffffu, t1, o);
        }
        if (lane == 0) { reds[0][0] = t0; reds[1][0] = t1; }
    }
    __syncthreads();
    const float inv0 = 1.0f / reds[0][0], inv1 = 1.0f / reds[1][0];

    // scatter both rows via cidx (read once, used for both)
    const int* cidxb = g_cidx + b * ENC_LEN;
#pragma unroll
    for (int j = 0; j < 8; j++) {
        int idx = tid * 8 + j;
        if (idx < n) {
            int sorig = cidxb[idx];
            float w0 = e0[j] * inv0;
            float w1 = e1[j] * inv1;
            full0[sorig] = w0;
            full1[sorig] = w1;
            if (e0[j] > 0.f) {
                int p = atomicAdd(&cnt0, 1);
                if (p < 128) { sidx0[p] = sorig; sw0[p] = w0; }
            }
            if (e1[j] > 0.f) {
                int p = atomicAdd(&cnt1, 1);
                if (p < 128) { sidx1[p] = sorig; sw1[p] = w1; }
            }
        }
    }
    __syncthreads();

    // vectorized full-row stores for both rows
#pragma unroll
    for (int i = 0; i < 2; i++) {
        reinterpret_cast<float4*>(row0)[tid + i * 256] =
            reinterpret_cast<const float4*>(full0)[tid + i * 256];
        reinterpret_cast<float4*>(row1)[tid + i * 256] =
            reinterpret_cast<const float4*>(full1)[tid + i * 256];
    }

    // sparse attn gathers for both rows
    int nc0 = cnt0; if (nc0 > 128) nc0 = 128;
    int nc1 = cnt1; if (nc1 > 128) nc1 = 128;
    float a0 = 0.f, a1 = 0.f;
    for (int i = 0; i < nc0; i++)
        a0 += sw0[i] * enc[((size_t)sidx0[i] * BATCH + b) * HID + tid];
    for (int i = 0; i < nc1; i++)
        a1 += sw1[i] * enc[((size_t)sidx1[i] * BATCH + b) * HID + tid];
    attn[((size_t)d0 * BATCH + b) * HID + tid] = a0;
    attn[((size_t)d1 * BATCH + b) * HID + tid] = a1;
}

// =====================================================================
extern "C" void kernel_launch(void* const* d_in, const int* in_sizes, int n_in,
                              void* d_out, int out_size) {
    const float* enc = (const float*)d_in[0];   // (2048, 32, 256)
    const float* dec = (const float*)d_in[1];   // (512, 32, 256)
    const float* W   = (const float*)d_in[2];   // (256, 256)
    const int* mask  = (const int*)d_in[3];     // (2048, 32)

    float* attn = (float*)d_out;
    float* wts  = (float*)d_out + (size_t)DEC_LEN * BATCH * HID;

    static bool attr_done = false;
    if (!attr_done) {
        cudaFuncSetAttribute(k_score_mma, cudaFuncAttributeMaxDynamicSharedMemorySize, SMEM_TOTAL);
        cudaFuncSetAttribute(k_proj_mma, cudaFuncAttributeMaxDynamicSharedMemorySize, SMEM_TOTAL);
        attr_done = true;
    }

    k_prep_decw_scan<<<NDEC_BLOCKS + HID + BATCH, 256>>>(dec, W, mask);
    k_prep_enc<<<(ENC_LEN * BATCH * HID / 4) / 256, 256>>>(enc);
    k_proj_mma<<<dim3(HID / 128, (DEC_LEN * BATCH) / 128), 256, SMEM_TOTAL>>>();
    k_score_mma<<<dim3(ENC_LEN / 128, DEC_LEN / 128, BATCH), 256, SMEM_TOTAL>>>(wts);
    k_softmax_attn<<<BATCH * DEC_LEN / 2, 256>>>(enc, wts, attn);
}